// round 12
// baseline (speedup 1.0000x reference)
#include <cuda_runtime.h>
#include <cuda_fp16.h>
#include <math.h>
#include <stdint.h>

#define TT 2048
#define SS 2048
#define BB 16
#define DD 1024
#define KK2 2048

// hybrid GEMM1 quantization: qh8 = round(qh*127/5), ql8 = round(ql*512*127)
#define QH_SCALE (127.0f / 5.0f)
#define QL_SCALE (512.0f * 127.0f)
#define MD_SCALE (5.0f / (127.0f * 512.0f * 127.0f))

// ---------------- device scratch (static) ----------------
__device__ float  g_scores[(size_t)BB * TT * SS];   // 256 MiB
__device__ __half g_combH[(size_t)BB * TT * KK2];   // [b][t][0..1023]=mix, [1024..2047]=q(hi)
__device__ __half g_cH[(size_t)BB * SS * DD];       // context hi [b][s][d]  (GEMM1 B)
__device__ __half g_cTH[(size_t)BB * DD * SS];      // context^T hi [b][d][s] (GEMM2 B)
__device__ __half g_PH[(size_t)BB * TT * SS];       // probs
__device__ __half g_WH[(size_t)DD * KK2];
__device__ int8_t g_qh8[(size_t)BB * TT * DD];      // quantized q hi
__device__ int8_t g_ql8[(size_t)BB * TT * DD];      // quantized q residual
__device__ int8_t g_ch8[(size_t)BB * SS * DD];      // quantized c hi
__device__ int8_t g_cl8[(size_t)BB * SS * DD];      // quantized c residual

// ---------------- helpers ----------------
__device__ __forceinline__ uint32_t smem_u32(const void* p) {
    uint32_t a;
    asm("{ .reg .u64 t; cvta.to.shared.u64 t, %1; cvt.u32.u64 %0, t; }" : "=r"(a) : "l"(p));
    return a;
}

__device__ __forceinline__ void ldsm4(uint32_t* r, uint32_t addr) {
    asm volatile("ldmatrix.sync.aligned.m8n8.x4.shared.b16 {%0,%1,%2,%3}, [%4];"
                 : "=r"(r[0]), "=r"(r[1]), "=r"(r[2]), "=r"(r[3]) : "r"(addr));
}

__device__ __forceinline__ void mma_f16(float* c, const uint32_t* a, uint32_t b0, uint32_t b1) {
    asm volatile(
        "mma.sync.aligned.m16n8k16.row.col.f32.f16.f16.f32 "
        "{%0,%1,%2,%3}, {%4,%5,%6,%7}, {%8,%9}, {%0,%1,%2,%3};"
        : "+f"(c[0]), "+f"(c[1]), "+f"(c[2]), "+f"(c[3])
        : "r"(a[0]), "r"(a[1]), "r"(a[2]), "r"(a[3]), "r"(b0), "r"(b1));
}

__device__ __forceinline__ void mma_i8(int* c, const uint32_t* a, uint32_t b0, uint32_t b1) {
    asm volatile(
        "mma.sync.aligned.m16n8k32.row.col.s32.s8.s8.s32 "
        "{%0,%1,%2,%3}, {%4,%5,%6,%7}, {%8,%9}, {%0,%1,%2,%3};"
        : "+r"(c[0]), "+r"(c[1]), "+r"(c[2]), "+r"(c[3])
        : "r"(a[0]), "r"(a[1]), "r"(a[2]), "r"(a[3]), "r"(b0), "r"(b1));
}

// 64B logical rows, 2 rows per 128B line (validated R3..R11)
__device__ __forceinline__ uint32_t sw_off32(int r, int c16) {
    uint32_t line = (uint32_t)(r >> 1);
    uint32_t sub = (uint32_t)(c16 + ((r & 1) << 2));
    return (line << 7) + ((sub ^ (line & 7)) << 4);
}
// 128B rows, 8-sub XOR swizzle (validated R4..R11)
__device__ __forceinline__ uint32_t sw_off64(int r, int c16) {
    return ((uint32_t)r << 7) + (((uint32_t)(c16 ^ (r & 7))) << 4);
}

__device__ __forceinline__ int clip8(float x) {
    int i = __float2int_rn(x);
    return max(-127, min(127, i));
}

__device__ __forceinline__ uint32_t pk4(int a, int b, int c, int d) {
    return (uint32_t)(a & 255) | ((uint32_t)(b & 255) << 8) |
           ((uint32_t)(c & 255) << 16) | ((uint32_t)(d & 255) << 24);
}

// ================= GEMM1: hybrid fp16 + int8-correction scores =================
// score = qh.ch (fp16 mma, fp32 acc) + MD_SCALE * (Qh8.Cl8 + Ql8.Ch8)
// CTA tile M128 x N64, 8 warps (4x2, warp 32x32), KC=64, NSTG=2, 2 CTAs/SM.
#define HYB_STAGE 49152
#define SMEM_HYB (2 * HYB_STAGE)
// stage layout: AF 0(16K) QH8 16K(8K) QL8 24K(8K) BF 32K(8K) CH8 40K(4K) CL8 44K(4K)
#define AF_OFF 0u
#define QH8_OFF 16384u
#define QL8_OFF 24576u
#define BF_OFF 32768u
#define CH8_OFF 40960u
#define CL8_OFF 45056u

__global__ __launch_bounds__(256, 2) void gemm_qk_hyb(
    const __half* __restrict__ Af,   // combH + DD, row stride KK2
    const int8_t* __restrict__ Aq1, const int8_t* __restrict__ Aq2,  // stride DD
    const __half* __restrict__ Bf,   // cH, stride DD
    const int8_t* __restrict__ Bq1, const int8_t* __restrict__ Bq2,  // stride DD
    float* __restrict__ outF) {
    extern __shared__ char smem[];
    const uint32_t sb = smem_u32(smem);
    const int tid = threadIdx.x;
    const int lane = tid & 31, wid = tid >> 5;
    const int wm = wid & 3, wn = wid >> 2;  // 4x2, warp 32x32
    const int n0 = blockIdx.x * 64, m0 = blockIdx.y * 128, bz = blockIdx.z;

    const __half* A_f = Af + ((size_t)bz * TT + m0) * KK2;
    const int8_t* A_1 = Aq1 + ((size_t)bz * TT + m0) * DD;
    const int8_t* A_2 = Aq2 + ((size_t)bz * TT + m0) * DD;
    const __half* B_f = Bf + ((size_t)bz * SS + n0) * DD;
    const int8_t* B_1 = Bq1 + ((size_t)bz * SS + n0) * DD;
    const int8_t* B_2 = Bq2 + ((size_t)bz * SS + n0) * DD;

    auto load_stage = [&](int c) {
        const int kk = c * 64;
        const uint32_t st = sb + (uint32_t)(c & 1) * HYB_STAGE;
        // AF: 128 rows x 128B (64 half) -> 1024 chunks
#pragma unroll
        for (int i = tid; i < 1024; i += 256) {
            const int r = i >> 3, cc = i & 7;
            asm volatile("cp.async.cg.shared.global [%0], [%1], 16;"
                         :: "r"(st + AF_OFF + sw_off64(r, cc)),
                            "l"((const char*)(A_f + (size_t)r * KK2 + kk) + (cc << 4)) : "memory");
        }
        // QH8/QL8: 128 rows x 64B -> 512 chunks each
#pragma unroll
        for (int i = tid; i < 512; i += 256) {
            const int r = i >> 2, cc = i & 3;
            asm volatile("cp.async.cg.shared.global [%0], [%1], 16;"
                         :: "r"(st + QH8_OFF + sw_off32(r, cc)),
                            "l"(A_1 + (size_t)r * DD + kk + (cc << 4)) : "memory");
            asm volatile("cp.async.cg.shared.global [%0], [%1], 16;"
                         :: "r"(st + QL8_OFF + sw_off32(r, cc)),
                            "l"(A_2 + (size_t)r * DD + kk + (cc << 4)) : "memory");
        }
        // BF: 64 rows x 128B -> 512 chunks
#pragma unroll
        for (int i = tid; i < 512; i += 256) {
            const int r = i >> 3, cc = i & 7;
            asm volatile("cp.async.cg.shared.global [%0], [%1], 16;"
                         :: "r"(st + BF_OFF + sw_off64(r, cc)),
                            "l"((const char*)(B_f + (size_t)r * DD + kk) + (cc << 4)) : "memory");
        }
        // CH8/CL8: 64 rows x 64B -> 256 chunks each
        {
            const int r = tid >> 2, cc = tid & 3;
            if (r < 64) {
                asm volatile("cp.async.cg.shared.global [%0], [%1], 16;"
                             :: "r"(st + CH8_OFF + sw_off32(r, cc)),
                                "l"(B_1 + (size_t)r * DD + kk + (cc << 4)) : "memory");
                asm volatile("cp.async.cg.shared.global [%0], [%1], 16;"
                             :: "r"(st + CL8_OFF + sw_off32(r, cc)),
                                "l"(B_2 + (size_t)r * DD + kk + (cc << 4)) : "memory");
            }
        }
        asm volatile("cp.async.commit_group;" ::: "memory");
    };

    // ldmatrix base offsets
    uint32_t offAf[2], offBf[2], offAi[2], offBi[2];
    {
        const int gA = lane >> 4;
#pragma unroll
        for (int mi = 0; mi < 2; mi++) {
            const int r = wm * 32 + mi * 16 + (lane & 15);
            offAf[mi] = sw_off64(r, gA);
            offAi[mi] = sw_off32(r, gA);
        }
        const int gB = (lane >> 3) & 1;
        const int rb = wn * 32 + ((lane >> 4) << 3) + (lane & 7);
#pragma unroll
        for (int g = 0; g < 2; g++) {
            offBf[g] = sw_off64(rb + g * 16, gB);
            offBi[g] = sw_off32(rb + g * 16, gB);
        }
    }

    float accf[2][4][4];
    int md[2][4][4];
#pragma unroll
    for (int i = 0; i < 2; i++)
#pragma unroll
        for (int j = 0; j < 4; j++)
#pragma unroll
            for (int q = 0; q < 4; q++) { accf[i][j][q] = 0.0f; md[i][j][q] = 0; }

    load_stage(0);

    const int KCH = DD / 64;  // 16
    for (int c = 0; c < KCH; c++) {
        asm volatile("cp.async.wait_group 0;" ::: "memory");
        __syncthreads();
        if (c + 1 < KCH) load_stage(c + 1);
        else asm volatile("cp.async.commit_group;" ::: "memory");

        const uint32_t st = sb + (uint32_t)(c & 1) * HYB_STAGE;
#pragma unroll
        for (int kb = 0; kb < 2; kb++) {  // two k32 blocks per 64-k chunk
            const uint32_t x32 = (uint32_t)(kb << 5);
            // ---- int8 corrections: Qh8.Cl8 + Ql8.Ch8 ----
            uint32_t aq1[2][4], aq2[2][4];
            ldsm4(aq1[0], st + QH8_OFF + (offAi[0] ^ x32));
            ldsm4(aq1[1], st + QH8_OFF + (offAi[1] ^ x32));
            ldsm4(aq2[0], st + QL8_OFF + (offAi[0] ^ x32));
            ldsm4(aq2[1], st + QL8_OFF + (offAi[1] ^ x32));
#pragma unroll
            for (int g = 0; g < 2; g++) {
                uint32_t bc1[4], bc2[4];
                ldsm4(bc1, st + CH8_OFF + (offBi[g] ^ x32));
                ldsm4(bc2, st + CL8_OFF + (offBi[g] ^ x32));
#pragma unroll
                for (int mi = 0; mi < 2; mi++) {
                    mma_i8(md[mi][2 * g], aq1[mi], bc2[0], bc2[1]);
                    mma_i8(md[mi][2 * g + 1], aq1[mi], bc2[2], bc2[3]);
                    mma_i8(md[mi][2 * g], aq2[mi], bc1[0], bc1[1]);
                    mma_i8(md[mi][2 * g + 1], aq2[mi], bc1[2], bc1[3]);
                }
            }
            // ---- fp16 main product: qh.ch (two k16 steps) ----
#pragma unroll
            for (int s = 0; s < 2; s++) {
                const uint32_t x16 = (uint32_t)((kb * 2 + s) << 5);
                uint32_t ah[2][4];
                ldsm4(ah[0], st + AF_OFF + (offAf[0] ^ x16));
                ldsm4(ah[1], st + AF_OFF + (offAf[1] ^ x16));
#pragma unroll
                for (int g = 0; g < 2; g++) {
                    uint32_t bh[4];
                    ldsm4(bh, st + BF_OFF + (offBf[g] ^ x16));
#pragma unroll
                    for (int mi = 0; mi < 2; mi++) {
                        mma_f16(accf[mi][2 * g], ah[mi], bh[0], bh[1]);
                        mma_f16(accf[mi][2 * g + 1], ah[mi], bh[2], bh[3]);
                    }
                }
            }
        }
    }

    // epilogue: combine + streaming stores
    const int trow = lane >> 2, tcol = (lane & 3) * 2;
#pragma unroll
    for (int mi = 0; mi < 2; mi++) {
#pragma unroll
        for (int nj = 0; nj < 4; nj++) {
            const int row = m0 + wm * 32 + mi * 16 + trow;
            const int col = n0 + wn * 32 + nj * 8 + tcol;
            float* p = outF + ((size_t)bz * TT + row) * SS + col;
            const float* f = accf[mi][nj];
            const int* m = md[mi][nj];
            __stcs((float2*)p,
                   make_float2(f[0] + MD_SCALE * (float)m[0], f[1] + MD_SCALE * (float)m[1]));
            __stcs((float2*)(p + 8 * SS),
                   make_float2(f[2] + MD_SCALE * (float)m[2], f[3] + MD_SCALE * (float)m[3]));
        }
    }
}

// ---------------- fp16 mma.sync GEMM (1-pass, unchanged from R10) ----------------
template <int EPI>
__global__ __launch_bounds__(256, 2) void mma_gemm(
    const __half* __restrict__ Ah, size_t a_row, size_t a_batch,
    const __half* __restrict__ Bh, size_t b_row, size_t b_batch,
    int KCH,
    float* __restrict__ outF, __half* __restrict__ outH,
    size_t c_row, size_t c_batch, const float* __restrict__ bias) {
    constexpr int NSTG = 3;
    constexpr uint32_t TILE_B = 32768;  // 128 rows x 128B (KC64 fp16) x2 tiles -> stage
    constexpr uint32_t STAGE_B = TILE_B;  // A 16KB + B 16KB
    constexpr uint32_t BH_OFF = 16384;

    extern __shared__ char smem[];
    const uint32_t sb = smem_u32(smem);
    const int tid = threadIdx.x;
    const int lane = tid & 31, wid = tid >> 5;
    const int wm = wid & 3, wn = wid >> 2;
    const int n0 = blockIdx.x * 128, m0 = blockIdx.y * 128, bz = blockIdx.z;

    const __half* A_h = Ah + (size_t)bz * a_batch + (size_t)m0 * a_row;
    const __half* B_h = Bh + (size_t)bz * b_batch + (size_t)n0 * b_row;

    auto load_stage = [&](int c) {
        const int kk = c * 64;
        const uint32_t st = sb + (uint32_t)(c % NSTG) * STAGE_B;
#pragma unroll
        for (int i = tid; i < 1024; i += 256) {
            const int r = i >> 3, cc = i & 7;
            asm volatile("cp.async.cg.shared.global [%0], [%1], 16;"
                         :: "r"(st + sw_off64(r, cc)),
                            "l"((const char*)(A_h + (size_t)r * a_row + kk) + (cc << 4)) : "memory");
        }
#pragma unroll
        for (int i = tid; i < 1024; i += 256) {
            const int r = i >> 3, cc = i & 7;
            asm volatile("cp.async.cg.shared.global [%0], [%1], 16;"
                         :: "r"(st + BH_OFF + sw_off64(r, cc)),
                            "l"((const char*)(B_h + (size_t)r * b_row + kk) + (cc << 4)) : "memory");
        }
        asm volatile("cp.async.commit_group;" ::: "memory");
    };

    uint32_t offA[2], offB[4];
    {
        const int gA = lane >> 4;
#pragma unroll
        for (int mi = 0; mi < 2; mi++)
            offA[mi] = sw_off64(wm * 32 + mi * 16 + (lane & 15), gA);
        const int gB = (lane >> 3) & 1;
        const int rb = wn * 64 + ((lane >> 4) << 3) + (lane & 7);
#pragma unroll
        for (int nj = 0; nj < 4; nj++) offB[nj] = sw_off64(rb + nj * 16, gB);
    }

    float acc[2][8][4];
#pragma unroll
    for (int i = 0; i < 2; i++)
#pragma unroll
        for (int j = 0; j < 8; j++)
#pragma unroll
            for (int q = 0; q < 4; q++) acc[i][j][q] = 0.0f;

    load_stage(0);
    load_stage(1);

    for (int c = 0; c < KCH; c++) {
        asm volatile("cp.async.wait_group 1;" ::: "memory");
        __syncthreads();
        if (c + 2 < KCH) load_stage(c + 2);
        else asm volatile("cp.async.commit_group;" ::: "memory");

        const uint32_t st = sb + (uint32_t)(c % NSTG) * STAGE_B;
#pragma unroll
        for (int k16 = 0; k16 < 4; k16++) {
            const uint32_t x = (uint32_t)(k16 << 5);
            uint32_t ah[2][4];
            ldsm4(ah[0], st + (offA[0] ^ x));
            ldsm4(ah[1], st + (offA[1] ^ x));
#pragma unroll
            for (int nj = 0; nj < 4; nj++) {
                uint32_t bh[4];
                ldsm4(bh, st + BH_OFF + (offB[nj] ^ x));
                mma_f16(acc[0][2 * nj], ah[0], bh[0], bh[1]);
                mma_f16(acc[0][2 * nj + 1], ah[0], bh[2], bh[3]);
                mma_f16(acc[1][2 * nj], ah[1], bh[0], bh[1]);
                mma_f16(acc[1][2 * nj + 1], ah[1], bh[2], bh[3]);
            }
        }
    }

    const int trow = lane >> 2, tcol = (lane & 3) * 2;
#pragma unroll
    for (int mi = 0; mi < 2; mi++) {
#pragma unroll
        for (int nj = 0; nj < 8; nj++) {
            const int row = m0 + wm * 32 + mi * 16 + trow;
            const int col = n0 + wn * 64 + nj * 8 + tcol;
            const float* a4 = acc[mi][nj];
            if (EPI == 1) {
                __half* ph = outH + (size_t)bz * c_batch + (size_t)row * c_row + col;
                __half2 vh;
                vh.x = __float2half_rn(a4[0]);
                vh.y = __float2half_rn(a4[1]);
                *(__half2*)ph = vh;
                vh.x = __float2half_rn(a4[2]);
                vh.y = __float2half_rn(a4[3]);
                *(__half2*)(ph + 8 * c_row) = vh;
            } else {
                const float b0 = bias[col], b1 = bias[col + 1];
                float* p = outF + (size_t)bz * c_batch + (size_t)row * c_row + col;
                *(float2*)p = make_float2(tanhf(a4[0] + b0), tanhf(a4[1] + b1));
                *(float2*)(p + 8 * c_row) = make_float2(tanhf(a4[2] + b0), tanhf(a4[3] + b1));
            }
        }
    }
}

// ---------------- conversion kernels ----------------
__global__ __launch_bounds__(256) void conv_q(const float* __restrict__ Q) {
    size_t i4 = ((size_t)blockIdx.x * 256 + threadIdx.x) * 4;  // over T*B*D
    float4 v = *(const float4*)(Q + i4);
    int d = (int)(i4 & (DD - 1));
    size_t j = i4 >> 10;
    int b = (int)(j & (BB - 1));
    size_t t = j >> 4;
    size_t o = ((size_t)b * TT + t) * KK2 + DD + d;
    const float* f = (const float*)&v;
    __half h[4];
    int q1[4], q2[4];
#pragma unroll
    for (int k = 0; k < 4; k++) {
        h[k] = __float2half_rn(f[k]);
        float hf = __half2float(h[k]);
        q1[k] = clip8(hf * QH_SCALE);
        q2[k] = clip8((f[k] - hf) * QL_SCALE);
    }
    __half2 vh;
    vh.x = h[0]; vh.y = h[1];
    *(__half2*)(g_combH + o) = vh;
    vh.x = h[2]; vh.y = h[3];
    *(__half2*)(g_combH + o + 2) = vh;
    size_t oq = ((size_t)b * TT + t) * DD + d;
    *(uint32_t*)(g_qh8 + oq) = pk4(q1[0], q1[1], q1[2], q1[3]);
    *(uint32_t*)(g_ql8 + oq) = pk4(q2[0], q2[1], q2[2], q2[3]);
}

__global__ __launch_bounds__(256) void conv_c_ct(const float* __restrict__ C) {
    __shared__ float tile[32][33];
    const int b = blockIdx.z;
    const int d0 = blockIdx.x * 32, s0 = blockIdx.y * 32;
    const int tx = threadIdx.x, ty = threadIdx.y;  // (32,8)
#pragma unroll
    for (int i = 0; i < 4; i++) {
        int s = s0 + ty + i * 8;
        float v = C[((size_t)s * BB + b) * DD + d0 + tx];
        tile[ty + i * 8][tx] = v;
        __half h = __float2half_rn(v);
        float hf = __half2float(h);
        size_t o = ((size_t)b * SS + s) * DD + d0 + tx;
        g_cH[o] = h;
        g_ch8[o] = (int8_t)clip8(hf * QH_SCALE);
        g_cl8[o] = (int8_t)clip8((v - hf) * QL_SCALE);
    }
    __syncthreads();
#pragma unroll
    for (int i = 0; i < 4; i++) {
        int d = d0 + ty + i * 8;
        size_t o = ((size_t)b * DD + d) * SS + s0 + tx;
        g_cTH[o] = __float2half_rn(tile[tx][ty + i * 8]);
    }
}

__global__ __launch_bounds__(256) void conv_w(const float* __restrict__ W) {
    size_t i4 = ((size_t)blockIdx.x * 256 + threadIdx.x) * 4;  // over D*2D
    float4 v = *(const float4*)(W + i4);
    __half2 vh;
    vh.x = __float2half_rn(v.x);
    vh.y = __float2half_rn(v.y);
    *(__half2*)(g_WH + i4) = vh;
    vh.x = __float2half_rn(v.z);
    vh.y = __float2half_rn(v.w);
    *(__half2*)(g_WH + i4 + 2) = vh;
}

// ---------------- softmax (==0 -> -inf mask), fp32 scores -> fp16 probs ----------------
__global__ __launch_bounds__(256) void softmax_mask() {
    const size_t rowi = blockIdx.x;
    const float4* p4 = (const float4*)(g_scores + rowi * SS);
    __half2* ph2 = (__half2*)(g_PH + rowi * SS);
    const int tid = threadIdx.x;
    const int lane = tid & 31, wid = tid >> 5;
    __shared__ float red[256];
    float4 v[2];
    float m = -INFINITY;
#pragma unroll
    for (int i = 0; i < 2; i++) {
        v[i] = __ldcs(&p4[tid + i * 256]);
        float* f = (float*)&v[i];
#pragma unroll
        for (int q = 0; q < 4; q++) {
            float x = (f[q] == 0.0f) ? -INFINITY : f[q];
            m = fmaxf(m, x);
        }
    }
    // max: warp shuffle (order-exact) + cross-warp via smem
#pragma unroll
    for (int off = 16; off > 0; off >>= 1)
        m = fmaxf(m, __shfl_xor_sync(0xffffffffu, m, off));
    if (lane == 0) red[wid] = m;
    __syncthreads();
    m = red[0];
#pragma unroll
    for (int w = 1; w < 8; w++) m = fmaxf(m, red[w]);
    __syncthreads();
    // exp + sum (tree kept bit-identical to prior rounds)
    float e[8];
    float sum = 0.0f;
#pragma unroll
    for (int i = 0; i < 2; i++) {
        float* f = (float*)&v[i];
#pragma unroll
        for (int q = 0; q < 4; q++) {
            float x = (f[q] == 0.0f) ? 0.0f : __expf(f[q] - m);
            e[i * 4 + q] = x;
            sum += x;
        }
    }
    red[tid] = sum;
    __syncthreads();
#pragma unroll
    for (int s = 128; s > 0; s >>= 1) {
        if (tid < s) red[tid] += red[tid + s];
        __syncthreads();
    }
    const float inv = 1.0f / red[0];
#pragma unroll
    for (int i = 0; i < 2; i++) {
#pragma unroll
        for (int q = 0; q < 2; q++) {
            __half2 vh;
            vh.x = __float2half_rn(e[i * 4 + q * 2] * inv);
            vh.y = __float2half_rn(e[i * 4 + q * 2 + 1] * inv);
            ph2[(tid + i * 256) * 2 + q] = vh;
        }
    }
}

// ---------------- launch ----------------
#define SMEM_G23 98304  // 3 stages x 32KB

extern "C" void kernel_launch(void* const* d_in, const int* in_sizes, int n_in,
                              void* d_out, int out_size) {
    (void)in_sizes; (void)n_in; (void)out_size;
    const float* Q = (const float*)d_in[0];
    const float* C = (const float*)d_in[1];
    const float* W = (const float*)d_in[2];
    const float* bias = (const float*)d_in[3];
    float* out = (float*)d_out;

    void *pScores, *pCombH, *pCH, *pCTH, *pPH, *pWH, *pQ1, *pQ2, *pC1, *pC2;
    cudaGetSymbolAddress(&pScores, g_scores);
    cudaGetSymbolAddress(&pCombH, g_combH);
    cudaGetSymbolAddress(&pCH, g_cH);
    cudaGetSymbolAddress(&pCTH, g_cTH);
    cudaGetSymbolAddress(&pPH, g_PH);
    cudaGetSymbolAddress(&pWH, g_WH);
    cudaGetSymbolAddress(&pQ1, g_qh8);
    cudaGetSymbolAddress(&pQ2, g_ql8);
    cudaGetSymbolAddress(&pC1, g_ch8);
    cudaGetSymbolAddress(&pC2, g_cl8);

    cudaFuncSetAttribute((const void*)gemm_qk_hyb, cudaFuncAttributeMaxDynamicSharedMemorySize, SMEM_HYB);
    cudaFuncSetAttribute((const void*)mma_gemm<1>, cudaFuncAttributeMaxDynamicSharedMemorySize, SMEM_G23);
    cudaFuncSetAttribute((const void*)mma_gemm<2>, cudaFuncAttributeMaxDynamicSharedMemorySize, SMEM_G23);

    // conversions
    conv_q<<<(unsigned)((size_t)TT * BB * DD / 1024), 256>>>(Q);
    conv_c_ct<<<dim3(DD / 32, SS / 32, BB), dim3(32, 8)>>>(C);
    conv_w<<<(unsigned)((size_t)DD * KK2 / 1024), 256>>>(W);

    // GEMM1: hybrid exact scores
    gemm_qk_hyb<<<dim3(SS / 64, TT / 128, BB), 256, SMEM_HYB>>>(
        (const __half*)pCombH + DD,
        (const int8_t*)pQ1, (const int8_t*)pQ2,
        (const __half*)pCH,
        (const int8_t*)pC1, (const int8_t*)pC2,
        (float*)pScores);

    softmax_mask<<<BB * TT, 256>>>();

    // GEMM2: mix = P . cT (1-pass fp16) -> fp16 into comb cols [0,1024)
    mma_gemm<1><<<dim3(DD / 128, TT / 128, BB), 256, SMEM_G23>>>(
        (const __half*)pPH, (size_t)SS, (size_t)TT * SS,
        (const __half*)pCTH, (size_t)SS, (size_t)DD * SS,
        SS / 64,
        nullptr, (__half*)pCombH, (size_t)KK2, (size_t)TT * KK2, nullptr);

    // GEMM3: out = tanh(comb . W^T + bias)  (1-pass fp16)
    mma_gemm<2><<<dim3(DD / 128, TT / 128, BB), 256, SMEM_G23>>>(
        (const __half*)pCombH, (size_t)KK2, (size_t)TT * KK2,
        (const __half*)pWH, (size_t)KK2, (size_t)0,
        KK2 / 64,
        out, nullptr, (size_t)DD, (size_t)TT * DD, bias);
}

// round 14
// speedup vs baseline: 2.1003x; 2.1003x over previous
#include <cuda_runtime.h>
#include <cuda_fp16.h>
#include <math.h>
#include <stdint.h>

#define TT 2048
#define SS 2048
#define BB 16
#define DD 1024
#define KK2 2048

// ---------------- device scratch (static) ----------------
__device__ float  g_scores[(size_t)BB * TT * SS];   // 256 MiB
__device__ __half g_combH[(size_t)BB * TT * KK2];   // [b][t][0..1023]=mix, [1024..2047]=q
__device__ __half g_combL[(size_t)BB * TT * KK2];   // lo: only q-half used (GEMM1 A)
__device__ __half g_cH[(size_t)BB * SS * DD];       // context hi [b][s][d]
__device__ __half g_cTH[(size_t)BB * DD * SS];      // context^T hi [b][d][s]
__device__ __half g_PH[(size_t)BB * TT * SS];       // probs hi
__device__ __half g_WH[(size_t)DD * KK2];

// ---------------- helpers ----------------
__device__ __forceinline__ void split2(float x, __half& h, __half& l) {
    h = __float2half_rn(x);
    l = __float2half_rn(x - __half2float(h));
}

__device__ __forceinline__ uint32_t smem_u32(const void* p) {
    uint32_t a;
    asm("{ .reg .u64 t; cvta.to.shared.u64 t, %1; cvt.u32.u64 %0, t; }" : "=r"(a) : "l"(p));
    return a;
}

__device__ __forceinline__ void ldsm4(uint32_t* r, uint32_t addr) {
    asm volatile("ldmatrix.sync.aligned.m8n8.x4.shared.b16 {%0,%1,%2,%3}, [%4];"
                 : "=r"(r[0]), "=r"(r[1]), "=r"(r[2]), "=r"(r[3]) : "r"(addr));
}

__device__ __forceinline__ void mma_f16(float* c, const uint32_t* a, uint32_t b0, uint32_t b1) {
    asm volatile(
        "mma.sync.aligned.m16n8k16.row.col.f32.f16.f16.f32 "
        "{%0,%1,%2,%3}, {%4,%5,%6,%7}, {%8,%9}, {%0,%1,%2,%3};"
        : "+f"(c[0]), "+f"(c[1]), "+f"(c[2]), "+f"(c[3])
        : "r"(a[0]), "r"(a[1]), "r"(a[2]), "r"(a[3]), "r"(b0), "r"(b1));
}

// KC=32: 64B logical rows, 2 rows per 128B line (validated R3..R12)
__device__ __forceinline__ uint32_t sw_off32(int r, int c16) {
    uint32_t line = (uint32_t)(r >> 1);
    uint32_t sub = (uint32_t)(c16 + ((r & 1) << 2));
    return (line << 7) + ((sub ^ (line & 7)) << 4);
}
// KC=64: 128B rows, 8-sub XOR swizzle (validated R4..R12)
__device__ __forceinline__ uint32_t sw_off64(int r, int c16) {
    return ((uint32_t)r << 7) + (((uint32_t)(c16 ^ (r & 7))) << 4);
}

// ---------------- fused split-precision fp16 mma.sync GEMM ----------------
// NP=2: Ah*Bh + Al*Bh     NP=1: Ah*Bh
// CTA tile M128 x N128, 8 warps (4x2, warp 32x64), 2 CTAs/SM.
// EPI: 0 = fp32 streaming store (scores), 1 = fp16 store, 2 = bias+tanh fp32.
template <int EPI, int NP, int KC>
__global__ __launch_bounds__(256, 2) void mma_gemm(
    const __half* __restrict__ Ah, const __half* __restrict__ Al,
    size_t a_row, size_t a_batch,
    const __half* __restrict__ Bh,
    size_t b_row, size_t b_batch,
    int KCH,  // K / KC
    float* __restrict__ outF, __half* __restrict__ outH,
    size_t c_row, size_t c_batch, const float* __restrict__ bias) {
    constexpr int NT = (NP == 2) ? 3 : 2;  // tiles per stage
    constexpr int NSTG = (NP == 2) ? ((KC == 32) ? 4 : 2) : 3;
    constexpr uint32_t TILE_B = 128 * KC * 2;
    constexpr uint32_t STAGE_B = NT * TILE_B;
    constexpr uint32_t AL_OFF = TILE_B;
    constexpr uint32_t BH_OFF = (NP == 2) ? 2 * TILE_B : TILE_B;
    constexpr int CPR = KC / 8;
    constexpr int NCHUNK = 128 * CPR;
    constexpr int NK16 = KC / 16;

    extern __shared__ char smem[];
    const uint32_t sb = smem_u32(smem);
    const int tid = threadIdx.x;
    const int lane = tid & 31, wid = tid >> 5;
    const int wm = wid & 3, wn = wid >> 2;
    const int n0 = blockIdx.x * 128, m0 = blockIdx.y * 128, bz = blockIdx.z;

    const __half* A_h = Ah + (size_t)bz * a_batch + (size_t)m0 * a_row;
    const __half* A_l = (NP == 2) ? (Al + (size_t)bz * a_batch + (size_t)m0 * a_row) : nullptr;
    const __half* B_h = Bh + (size_t)bz * b_batch + (size_t)n0 * b_row;

    auto swz = [](int r, int c16) {
        return (KC == 32) ? sw_off32(r, c16) : sw_off64(r, c16);
    };

    auto load_tile = [&](uint32_t dst, const __half* g, size_t rstride, int kk) {
#pragma unroll
        for (int i = tid; i < NCHUNK; i += 256) {
            const int r = i / CPR, cc = i % CPR;
            const char* gp = (const char*)(g + (size_t)r * rstride + kk) + (cc << 4);
            asm volatile("cp.async.cg.shared.global [%0], [%1], 16;"
                         :: "r"(dst + swz(r, cc)), "l"(gp) : "memory");
        }
    };
    auto load_stage = [&](int c) {
        const int kk = c * KC;
        const uint32_t st = sb + (uint32_t)(c % NSTG) * STAGE_B;
        load_tile(st, A_h, a_row, kk);
        if (NP == 2) load_tile(st + AL_OFF, A_l, a_row, kk);
        load_tile(st + BH_OFF, B_h, b_row, kk);
        asm volatile("cp.async.commit_group;" ::: "memory");
    };

    // per-thread ldmatrix offsets (k16 step j via XOR j<<5)
    uint32_t offA[2], offB[4];
    {
        const int gA = lane >> 4;
#pragma unroll
        for (int mi = 0; mi < 2; mi++)
            offA[mi] = swz(wm * 32 + mi * 16 + (lane & 15), gA);
        const int gB = (lane >> 3) & 1;
        const int rb = wn * 64 + ((lane >> 4) << 3) + (lane & 7);
#pragma unroll
        for (int nj = 0; nj < 4; nj++) offB[nj] = swz(rb + nj * 16, gB);
    }

    float acc[2][8][4];
#pragma unroll
    for (int i = 0; i < 2; i++)
#pragma unroll
        for (int j = 0; j < 8; j++)
#pragma unroll
            for (int q = 0; q < 4; q++) acc[i][j][q] = 0.0f;

#pragma unroll
    for (int s = 0; s < NSTG - 1; s++) load_stage(s);

    for (int c = 0; c < KCH; c++) {
        asm volatile("cp.async.wait_group %0;" :: "n"(NSTG - 2) : "memory");
        __syncthreads();
        if (c + NSTG - 1 < KCH) load_stage(c + NSTG - 1);
        else asm volatile("cp.async.commit_group;" ::: "memory");

        const uint32_t st = sb + (uint32_t)(c % NSTG) * STAGE_B;
#pragma unroll
        for (int k16 = 0; k16 < NK16; k16++) {
            const uint32_t x = (uint32_t)(k16 << 5);
            uint32_t ah[2][4], al[2][4];
            ldsm4(ah[0], st + (offA[0] ^ x));
            ldsm4(ah[1], st + (offA[1] ^ x));
            if (NP == 2) {
                ldsm4(al[0], st + AL_OFF + (offA[0] ^ x));
                ldsm4(al[1], st + AL_OFF + (offA[1] ^ x));
            }
#pragma unroll
            for (int nj = 0; nj < 4; nj++) {
                uint32_t bh[4];
                ldsm4(bh, st + BH_OFF + (offB[nj] ^ x));
                mma_f16(acc[0][2 * nj], ah[0], bh[0], bh[1]);
                mma_f16(acc[0][2 * nj + 1], ah[0], bh[2], bh[3]);
                mma_f16(acc[1][2 * nj], ah[1], bh[0], bh[1]);
                mma_f16(acc[1][2 * nj + 1], ah[1], bh[2], bh[3]);
                if (NP == 2) {
                    mma_f16(acc[0][2 * nj], al[0], bh[0], bh[1]);
                    mma_f16(acc[0][2 * nj + 1], al[0], bh[2], bh[3]);
                    mma_f16(acc[1][2 * nj], al[1], bh[0], bh[1]);
                    mma_f16(acc[1][2 * nj + 1], al[1], bh[2], bh[3]);
                }
            }
        }
    }

    // -------- epilogue --------
    const int trow = lane >> 2, tcol = (lane & 3) * 2;
#pragma unroll
    for (int mi = 0; mi < 2; mi++) {
#pragma unroll
        for (int nj = 0; nj < 8; nj++) {
            const int row = m0 + wm * 32 + mi * 16 + trow;
            const int col = n0 + wn * 64 + nj * 8 + tcol;
            const float* a4 = acc[mi][nj];
            if (EPI == 0) {
                float* p = outF + (size_t)bz * c_batch + (size_t)row * c_row + col;
                __stcs((float2*)p, make_float2(a4[0], a4[1]));
                __stcs((float2*)(p + 8 * c_row), make_float2(a4[2], a4[3]));
            } else if (EPI == 1) {
                __half* ph = outH + (size_t)bz * c_batch + (size_t)row * c_row + col;
                __half2 vh;
                vh.x = __float2half_rn(a4[0]);
                vh.y = __float2half_rn(a4[1]);
                *(__half2*)ph = vh;
                vh.x = __float2half_rn(a4[2]);
                vh.y = __float2half_rn(a4[3]);
                *(__half2*)(ph + 8 * c_row) = vh;
            } else {
                const float b0 = bias[col], b1 = bias[col + 1];
                float* p = outF + (size_t)bz * c_batch + (size_t)row * c_row + col;
                *(float2*)p = make_float2(tanhf(a4[0] + b0), tanhf(a4[1] + b1));
                *(float2*)(p + 8 * c_row) = make_float2(tanhf(a4[2] + b0), tanhf(a4[3] + b1));
            }
        }
    }
}

// ---------------- conversion kernels (vectorized) ----------------
__global__ __launch_bounds__(256) void conv_q(const float* __restrict__ Q) {
    size_t i4 = ((size_t)blockIdx.x * 256 + threadIdx.x) * 4;  // over T*B*D
    float4 v = *(const float4*)(Q + i4);
    int d = (int)(i4 & (DD - 1));
    size_t j = i4 >> 10;
    int b = (int)(j & (BB - 1));
    size_t t = j >> 4;
    size_t o = ((size_t)b * TT + t) * KK2 + DD + d;
    __half h0, l0, h1, l1;
    __half2 vh, vl;
    split2(v.x, h0, l0); split2(v.y, h1, l1);
    vh.x = h0; vh.y = h1; vl.x = l0; vl.y = l1;
    *(__half2*)(g_combH + o) = vh;
    *(__half2*)(g_combL + o) = vl;
    split2(v.z, h0, l0); split2(v.w, h1, l1);
    vh.x = h0; vh.y = h1; vl.x = l0; vl.y = l1;
    *(__half2*)(g_combH + o + 2) = vh;
    *(__half2*)(g_combL + o + 2) = vl;
}

__global__ __launch_bounds__(256) void conv_c_ct(const float* __restrict__ C) {
    __shared__ float tile[32][33];
    const int b = blockIdx.z;
    const int d0 = blockIdx.x * 32, s0 = blockIdx.y * 32;
    const int tx = threadIdx.x, ty = threadIdx.y;  // (32,8)
#pragma unroll
    for (int i = 0; i < 4; i++) {
        int s = s0 + ty + i * 8;
        float v = C[((size_t)s * BB + b) * DD + d0 + tx];
        tile[ty + i * 8][tx] = v;
        size_t o = ((size_t)b * SS + s) * DD + d0 + tx;
        g_cH[o] = __float2half_rn(v);
    }
    __syncthreads();
#pragma unroll
    for (int i = 0; i < 4; i++) {
        int d = d0 + ty + i * 8;
        size_t o = ((size_t)b * DD + d) * SS + s0 + tx;
        g_cTH[o] = __float2half_rn(tile[tx][ty + i * 8]);
    }
}

__global__ __launch_bounds__(256) void conv_w(const float* __restrict__ W) {
    size_t i4 = ((size_t)blockIdx.x * 256 + threadIdx.x) * 4;  // over D*2D
    float4 v = *(const float4*)(W + i4);
    __half2 vh;
    vh.x = __float2half_rn(v.x);
    vh.y = __float2half_rn(v.y);
    *(__half2*)(g_WH + i4) = vh;
    vh.x = __float2half_rn(v.z);
    vh.y = __float2half_rn(v.w);
    *(__half2*)(g_WH + i4 + 2) = vh;
}

// ---------------- softmax (==0 -> -inf mask), fp32 scores -> fp16 probs ----------------
__global__ __launch_bounds__(256) void softmax_mask() {
    const size_t rowi = blockIdx.x;
    const float4* p4 = (const float4*)(g_scores + rowi * SS);
    __half2* ph2 = (__half2*)(g_PH + rowi * SS);
    const int tid = threadIdx.x;
    const int lane = tid & 31, wid = tid >> 5;
    __shared__ float red[256];
    float4 v[2];
    float m = -INFINITY;
#pragma unroll
    for (int i = 0; i < 2; i++) {
        v[i] = __ldcs(&p4[tid + i * 256]);
        float* f = (float*)&v[i];
#pragma unroll
        for (int q = 0; q < 4; q++) {
            float x = (f[q] == 0.0f) ? -INFINITY : f[q];
            m = fmaxf(m, x);
        }
    }
    // max: warp shuffle (order-exact) + cross-warp via smem (validated R12)
#pragma unroll
    for (int off = 16; off > 0; off >>= 1)
        m = fmaxf(m, __shfl_xor_sync(0xffffffffu, m, off));
    if (lane == 0) red[wid] = m;
    __syncthreads();
    m = red[0];
#pragma unroll
    for (int w = 1; w < 8; w++) m = fmaxf(m, red[w]);
    __syncthreads();
    // exp + sum (tree kept bit-identical to prior rounds)
    float e[8];
    float sum = 0.0f;
#pragma unroll
    for (int i = 0; i < 2; i++) {
        float* f = (float*)&v[i];
#pragma unroll
        for (int q = 0; q < 4; q++) {
            float x = (f[q] == 0.0f) ? 0.0f : __expf(f[q] - m);
            e[i * 4 + q] = x;
            sum += x;
        }
    }
    red[tid] = sum;
    __syncthreads();
#pragma unroll
    for (int s = 128; s > 0; s >>= 1) {
        if (tid < s) red[tid] += red[tid + s];
        __syncthreads();
    }
    const float inv = 1.0f / red[0];
#pragma unroll
    for (int i = 0; i < 2; i++) {
#pragma unroll
        for (int q = 0; q < 2; q++) {
            __half2 vh;
            vh.x = __float2half_rn(e[i * 4 + q * 2] * inv);
            vh.y = __float2half_rn(e[i * 4 + q * 2 + 1] * inv);
            ph2[(tid + i * 256) * 2 + q] = vh;
        }
    }
}

// ---------------- launch ----------------
#define SMEM_G1 98304   // NP2 KC32: 4 stages x 24KB
#define SMEM_G23 98304  // NP1 KC64: 3 stages x 32KB

extern "C" void kernel_launch(void* const* d_in, const int* in_sizes, int n_in,
                              void* d_out, int out_size) {
    (void)in_sizes; (void)n_in; (void)out_size;
    const float* Q = (const float*)d_in[0];
    const float* C = (const float*)d_in[1];
    const float* W = (const float*)d_in[2];
    const float* bias = (const float*)d_in[3];
    float* out = (float*)d_out;

    void *pScores, *pCombH, *pCombL, *pCH, *pCTH, *pPH, *pWH;
    cudaGetSymbolAddress(&pScores, g_scores);
    cudaGetSymbolAddress(&pCombH, g_combH);
    cudaGetSymbolAddress(&pCombL, g_combL);
    cudaGetSymbolAddress(&pCH, g_cH);
    cudaGetSymbolAddress(&pCTH, g_cTH);
    cudaGetSymbolAddress(&pPH, g_PH);
    cudaGetSymbolAddress(&pWH, g_WH);

    cudaFuncSetAttribute((const void*)mma_gemm<0, 2, 32>, cudaFuncAttributeMaxDynamicSharedMemorySize, SMEM_G1);
    cudaFuncSetAttribute((const void*)mma_gemm<1, 1, 64>, cudaFuncAttributeMaxDynamicSharedMemorySize, SMEM_G23);
    cudaFuncSetAttribute((const void*)mma_gemm<2, 1, 64>, cudaFuncAttributeMaxDynamicSharedMemorySize, SMEM_G23);

    // conversions
    conv_q<<<(unsigned)((size_t)TT * BB * DD / 1024), 256>>>(Q);
    conv_c_ct<<<dim3(DD / 32, SS / 32, BB), dim3(32, 8)>>>(C);
    conv_w<<<(unsigned)((size_t)DD * KK2 / 1024), 256>>>(W);

    // GEMM1: scores = q . c   (2-pass: qh*ch + ql*ch, KC32/NSTG4 deep pipeline)
    mma_gemm<0, 2, 32><<<dim3(SS / 128, TT / 128, BB), 256, SMEM_G1>>>(
        (const __half*)pCombH + DD, (const __half*)pCombL + DD,
        (size_t)KK2, (size_t)TT * KK2,
        (const __half*)pCH,
        (size_t)DD, (size_t)SS * DD,
        DD / 32,
        (float*)pScores, nullptr, (size_t)SS, (size_t)TT * SS, nullptr);

    softmax_mask<<<BB * TT, 256>>>();

    // GEMM2: mix = P . cT   (1-pass fp16, KC64/NSTG3) -> fp16 into comb cols [0,1024)
    mma_gemm<1, 1, 64><<<dim3(DD / 128, TT / 128, BB), 256, SMEM_G23>>>(
        (const __half*)pPH, nullptr,
        (size_t)SS, (size_t)TT * SS,
        (const __half*)pCTH,
        (size_t)SS, (size_t)DD * SS,
        SS / 64,
        nullptr, (__half*)pCombH, (size_t)KK2, (size_t)TT * KK2, nullptr);

    // GEMM3: out = tanh(comb . W^T + bias)   (1-pass fp16, KC64/NSTG3)
    mma_gemm<2, 1, 64><<<dim3(DD / 128, TT / 128, BB), 256, SMEM_G23>>>(
        (const __half*)pCombH, nullptr,
        (size_t)KK2, (size_t)TT * KK2,
        (const __half*)pWH,
        (size_t)KK2, (size_t)0,
        KK2 / 64,
        out, nullptr, (size_t)DD, (size_t)TT * DD, bias);
}

// round 15
// speedup vs baseline: 2.1734x; 1.0348x over previous
#include <cuda_runtime.h>
#include <cuda_fp16.h>
#include <math.h>
#include <stdint.h>

#define TT 2048
#define SS 2048
#define BB 16
#define DD 1024
#define KK2 2048

// ---------------- device scratch (static) ----------------
__device__ float  g_scores[(size_t)BB * TT * SS];   // 256 MiB
__device__ __half g_combH[(size_t)BB * TT * KK2];   // [b][t][0..1023]=mix, [1024..2047]=q
__device__ __half g_combL[(size_t)BB * TT * KK2];   // lo: only q-half used (GEMM1 A)
__device__ __half g_cH[(size_t)BB * SS * DD];       // context hi [b][s][d]
__device__ __half g_cTH[(size_t)BB * DD * SS];      // context^T hi [b][d][s]
__device__ __half g_PH[(size_t)BB * TT * SS];       // probs hi
__device__ __half g_WH[(size_t)DD * KK2];

// ---------------- helpers ----------------
__device__ __forceinline__ void split2(float x, __half& h, __half& l) {
    h = __float2half_rn(x);
    l = __float2half_rn(x - __half2float(h));
}

__device__ __forceinline__ uint32_t smem_u32(const void* p) {
    uint32_t a;
    asm("{ .reg .u64 t; cvta.to.shared.u64 t, %1; cvt.u32.u64 %0, t; }" : "=r"(a) : "l"(p));
    return a;
}

__device__ __forceinline__ void ldsm4(uint32_t* r, uint32_t addr) {
    asm volatile("ldmatrix.sync.aligned.m8n8.x4.shared.b16 {%0,%1,%2,%3}, [%4];"
                 : "=r"(r[0]), "=r"(r[1]), "=r"(r[2]), "=r"(r[3]) : "r"(addr));
}

__device__ __forceinline__ void mma_f16(float* c, const uint32_t* a, uint32_t b0, uint32_t b1) {
    asm volatile(
        "mma.sync.aligned.m16n8k16.row.col.f32.f16.f16.f32 "
        "{%0,%1,%2,%3}, {%4,%5,%6,%7}, {%8,%9}, {%0,%1,%2,%3};"
        : "+f"(c[0]), "+f"(c[1]), "+f"(c[2]), "+f"(c[3])
        : "r"(a[0]), "r"(a[1]), "r"(a[2]), "r"(a[3]), "r"(b0), "r"(b1));
}

// KC=64: 128B rows, 8-sub XOR swizzle (validated R4..R13)
__device__ __forceinline__ uint32_t sw_off64(int r, int c16) {
    return ((uint32_t)r << 7) + (((uint32_t)(c16 ^ (r & 7))) << 4);
}

// ---------------- fused split-precision fp16 mma.sync GEMM ----------------
// NP=2: Ah*Bh + Al*Bh     NP=1: Ah*Bh     (KC=64 only — the validated-best shape)
// CTA tile M128 x N128, 8 warps (4x2, warp 32x64), 2 CTAs/SM.
// EPI: 0 = fp32 streaming store (scores), 1 = fp16 store, 2 = bias+tanh fp32.
template <int EPI, int NP>
__global__ __launch_bounds__(256, 2) void mma_gemm(
    const __half* __restrict__ Ah, const __half* __restrict__ Al,
    size_t a_row, size_t a_batch,
    const __half* __restrict__ Bh,
    size_t b_row, size_t b_batch,
    int KCH,  // K / 64
    float* __restrict__ outF, __half* __restrict__ outH,
    size_t c_row, size_t c_batch, const float* __restrict__ bias) {
    constexpr int NT = (NP == 2) ? 3 : 2;     // tiles per stage
    constexpr int NSTG = (NP == 2) ? 2 : 3;   // R10-validated ring depths
    constexpr uint32_t TILE_B = 16384;        // 128 rows x 128B
    constexpr uint32_t STAGE_B = NT * TILE_B;
    constexpr uint32_t AL_OFF = TILE_B;
    constexpr uint32_t BH_OFF = (NP == 2) ? 2 * TILE_B : TILE_B;

    extern __shared__ char smem[];
    const uint32_t sb = smem_u32(smem);
    const int tid = threadIdx.x;
    const int lane = tid & 31, wid = tid >> 5;
    const int wm = wid & 3, wn = wid >> 2;
    const int n0 = blockIdx.x * 128, m0 = blockIdx.y * 128, bz = blockIdx.z;

    const __half* A_h = Ah + (size_t)bz * a_batch + (size_t)m0 * a_row;
    const __half* A_l = (NP == 2) ? (Al + (size_t)bz * a_batch + (size_t)m0 * a_row) : nullptr;
    const __half* B_h = Bh + (size_t)bz * b_batch + (size_t)n0 * b_row;

    auto load_tile = [&](uint32_t dst, const __half* g, size_t rstride, int kk) {
#pragma unroll
        for (int i = tid; i < 1024; i += 256) {
            const int r = i >> 3, cc = i & 7;
            const char* gp = (const char*)(g + (size_t)r * rstride + kk) + (cc << 4);
            asm volatile("cp.async.cg.shared.global [%0], [%1], 16;"
                         :: "r"(dst + sw_off64(r, cc)), "l"(gp) : "memory");
        }
    };
    auto load_stage = [&](int c) {
        const int kk = c * 64;
        const uint32_t st = sb + (uint32_t)(c % NSTG) * STAGE_B;
        load_tile(st, A_h, a_row, kk);
        if (NP == 2) load_tile(st + AL_OFF, A_l, a_row, kk);
        load_tile(st + BH_OFF, B_h, b_row, kk);
        asm volatile("cp.async.commit_group;" ::: "memory");
    };

    // per-thread ldmatrix offsets (k16 step j via XOR j<<5)
    uint32_t offA[2], offB[4];
    {
        const int gA = lane >> 4;
#pragma unroll
        for (int mi = 0; mi < 2; mi++)
            offA[mi] = sw_off64(wm * 32 + mi * 16 + (lane & 15), gA);
        const int gB = (lane >> 3) & 1;
        const int rb = wn * 64 + ((lane >> 4) << 3) + (lane & 7);
#pragma unroll
        for (int nj = 0; nj < 4; nj++) offB[nj] = sw_off64(rb + nj * 16, gB);
    }

    float acc[2][8][4];
#pragma unroll
    for (int i = 0; i < 2; i++)
#pragma unroll
        for (int j = 0; j < 8; j++)
#pragma unroll
            for (int q = 0; q < 4; q++) acc[i][j][q] = 0.0f;

#pragma unroll
    for (int s = 0; s < NSTG - 1; s++) load_stage(s);

    for (int c = 0; c < KCH; c++) {
        asm volatile("cp.async.wait_group %0;" :: "n"(NSTG - 2) : "memory");
        __syncthreads();
        if (c + NSTG - 1 < KCH) load_stage(c + NSTG - 1);
        else asm volatile("cp.async.commit_group;" ::: "memory");

        const uint32_t st = sb + (uint32_t)(c % NSTG) * STAGE_B;
#pragma unroll
        for (int k16 = 0; k16 < 4; k16++) {
            const uint32_t x = (uint32_t)(k16 << 5);
            uint32_t ah[2][4], al[2][4];
            ldsm4(ah[0], st + (offA[0] ^ x));
            ldsm4(ah[1], st + (offA[1] ^ x));
            if (NP == 2) {
                ldsm4(al[0], st + AL_OFF + (offA[0] ^ x));
                ldsm4(al[1], st + AL_OFF + (offA[1] ^ x));
            }
#pragma unroll
            for (int nj = 0; nj < 4; nj++) {
                uint32_t bh[4];
                ldsm4(bh, st + BH_OFF + (offB[nj] ^ x));
                mma_f16(acc[0][2 * nj], ah[0], bh[0], bh[1]);
                mma_f16(acc[0][2 * nj + 1], ah[0], bh[2], bh[3]);
                mma_f16(acc[1][2 * nj], ah[1], bh[0], bh[1]);
                mma_f16(acc[1][2 * nj + 1], ah[1], bh[2], bh[3]);
                if (NP == 2) {
                    mma_f16(acc[0][2 * nj], al[0], bh[0], bh[1]);
                    mma_f16(acc[0][2 * nj + 1], al[0], bh[2], bh[3]);
                    mma_f16(acc[1][2 * nj], al[1], bh[0], bh[1]);
                    mma_f16(acc[1][2 * nj + 1], al[1], bh[2], bh[3]);
                }
            }
        }
    }

    // -------- epilogue --------
    const int trow = lane >> 2, tcol = (lane & 3) * 2;
#pragma unroll
    for (int mi = 0; mi < 2; mi++) {
#pragma unroll
        for (int nj = 0; nj < 8; nj++) {
            const int row = m0 + wm * 32 + mi * 16 + trow;
            const int col = n0 + wn * 64 + nj * 8 + tcol;
            const float* a4 = acc[mi][nj];
            if (EPI == 0) {
                float* p = outF + (size_t)bz * c_batch + (size_t)row * c_row + col;
                __stcs((float2*)p, make_float2(a4[0], a4[1]));
                __stcs((float2*)(p + 8 * c_row), make_float2(a4[2], a4[3]));
            } else if (EPI == 1) {
                __half* ph = outH + (size_t)bz * c_batch + (size_t)row * c_row + col;
                __half2 vh;
                vh.x = __float2half_rn(a4[0]);
                vh.y = __float2half_rn(a4[1]);
                *(__half2*)ph = vh;
                vh.x = __float2half_rn(a4[2]);
                vh.y = __float2half_rn(a4[3]);
                *(__half2*)(ph + 8 * c_row) = vh;
            } else {
                const float b0 = bias[col], b1 = bias[col + 1];
                float* p = outF + (size_t)bz * c_batch + (size_t)row * c_row + col;
                *(float2*)p = make_float2(tanhf(a4[0] + b0), tanhf(a4[1] + b1));
                *(float2*)(p + 8 * c_row) = make_float2(tanhf(a4[2] + b0), tanhf(a4[3] + b1));
            }
        }
    }
}

// ---------------- conversion kernels (vectorized) ----------------
__global__ __launch_bounds__(256) void conv_q(const float* __restrict__ Q) {
    size_t i4 = ((size_t)blockIdx.x * 256 + threadIdx.x) * 4;  // over T*B*D
    float4 v = *(const float4*)(Q + i4);
    int d = (int)(i4 & (DD - 1));
    size_t j = i4 >> 10;
    int b = (int)(j & (BB - 1));
    size_t t = j >> 4;
    size_t o = ((size_t)b * TT + t) * KK2 + DD + d;
    __half h0, l0, h1, l1;
    __half2 vh, vl;
    split2(v.x, h0, l0); split2(v.y, h1, l1);
    vh.x = h0; vh.y = h1; vl.x = l0; vl.y = l1;
    *(__half2*)(g_combH + o) = vh;
    *(__half2*)(g_combL + o) = vl;
    split2(v.z, h0, l0); split2(v.w, h1, l1);
    vh.x = h0; vh.y = h1; vl.x = l0; vl.y = l1;
    *(__half2*)(g_combH + o + 2) = vh;
    *(__half2*)(g_combL + o + 2) = vl;
}

__global__ __launch_bounds__(256) void conv_c_ct(const float* __restrict__ C) {
    __shared__ float tile[32][33];
    const int b = blockIdx.z;
    const int d0 = blockIdx.x * 32, s0 = blockIdx.y * 32;
    const int tx = threadIdx.x, ty = threadIdx.y;  // (32,8)
#pragma unroll
    for (int i = 0; i < 4; i++) {
        int s = s0 + ty + i * 8;
        float v = C[((size_t)s * BB + b) * DD + d0 + tx];
        tile[ty + i * 8][tx] = v;
        size_t o = ((size_t)b * SS + s) * DD + d0 + tx;
        g_cH[o] = __float2half_rn(v);
    }
    __syncthreads();
#pragma unroll
    for (int i = 0; i < 4; i++) {
        int d = d0 + ty + i * 8;
        size_t o = ((size_t)b * DD + d) * SS + s0 + tx;
        g_cTH[o] = __float2half_rn(tile[tx][ty + i * 8]);
    }
}

__global__ __launch_bounds__(256) void conv_w(const float* __restrict__ W) {
    size_t i4 = ((size_t)blockIdx.x * 256 + threadIdx.x) * 4;  // over D*2D
    float4 v = *(const float4*)(W + i4);
    __half2 vh;
    vh.x = __float2half_rn(v.x);
    vh.y = __float2half_rn(v.y);
    *(__half2*)(g_WH + i4) = vh;
    vh.x = __float2half_rn(v.z);
    vh.y = __float2half_rn(v.w);
    *(__half2*)(g_WH + i4 + 2) = vh;
}

// ---------------- softmax (==0 -> -inf mask), fp32 scores -> fp16 probs ----------------
__global__ __launch_bounds__(256) void softmax_mask() {
    const size_t rowi = blockIdx.x;
    const float4* p4 = (const float4*)(g_scores + rowi * SS);
    __half2* ph2 = (__half2*)(g_PH + rowi * SS);
    const int tid = threadIdx.x;
    const int lane = tid & 31, wid = tid >> 5;
    __shared__ float red[256];
    float4 v[2];
    float m = -INFINITY;
#pragma unroll
    for (int i = 0; i < 2; i++) {
        v[i] = __ldcs(&p4[tid + i * 256]);
        float* f = (float*)&v[i];
#pragma unroll
        for (int q = 0; q < 4; q++) {
            float x = (f[q] == 0.0f) ? -INFINITY : f[q];
            m = fmaxf(m, x);
        }
    }
    // max: warp shuffle (order-exact) + cross-warp via smem (validated R12/R13)
#pragma unroll
    for (int off = 16; off > 0; off >>= 1)
        m = fmaxf(m, __shfl_xor_sync(0xffffffffu, m, off));
    if (lane == 0) red[wid] = m;
    __syncthreads();
    m = red[0];
#pragma unroll
    for (int w = 1; w < 8; w++) m = fmaxf(m, red[w]);
    __syncthreads();
    // exp + sum (tree kept bit-identical to prior rounds)
    float e[8];
    float sum = 0.0f;
#pragma unroll
    for (int i = 0; i < 2; i++) {
        float* f = (float*)&v[i];
#pragma unroll
        for (int q = 0; q < 4; q++) {
            float x = (f[q] == 0.0f) ? 0.0f : __expf(f[q] - m);
            e[i * 4 + q] = x;
            sum += x;
        }
    }
    red[tid] = sum;
    __syncthreads();
#pragma unroll
    for (int s = 128; s > 0; s >>= 1) {
        if (tid < s) red[tid] += red[tid + s];
        __syncthreads();
    }
    const float inv = 1.0f / red[0];
#pragma unroll
    for (int i = 0; i < 2; i++) {
#pragma unroll
        for (int q = 0; q < 2; q++) {
            __half2 vh;
            vh.x = __float2half_rn(e[i * 4 + q * 2] * inv);
            vh.y = __float2half_rn(e[i * 4 + q * 2 + 1] * inv);
            ph2[(tid + i * 256) * 2 + q] = vh;
        }
    }
}

// ---------------- launch ----------------
#define SMEM_G1 98304   // NP2 KC64: 2 stages x 48KB  (R10-validated best)
#define SMEM_G23 98304  // NP1 KC64: 3 stages x 32KB

extern "C" void kernel_launch(void* const* d_in, const int* in_sizes, int n_in,
                              void* d_out, int out_size) {
    (void)in_sizes; (void)n_in; (void)out_size;
    const float* Q = (const float*)d_in[0];
    const float* C = (const float*)d_in[1];
    const float* W = (const float*)d_in[2];
    const float* bias = (const float*)d_in[3];
    float* out = (float*)d_out;

    void *pScores, *pCombH, *pCombL, *pCH, *pCTH, *pPH, *pWH;
    cudaGetSymbolAddress(&pScores, g_scores);
    cudaGetSymbolAddress(&pCombH, g_combH);
    cudaGetSymbolAddress(&pCombL, g_combL);
    cudaGetSymbolAddress(&pCH, g_cH);
    cudaGetSymbolAddress(&pCTH, g_cTH);
    cudaGetSymbolAddress(&pPH, g_PH);
    cudaGetSymbolAddress(&pWH, g_WH);

    cudaFuncSetAttribute((const void*)mma_gemm<0, 2>, cudaFuncAttributeMaxDynamicSharedMemorySize, SMEM_G1);
    cudaFuncSetAttribute((const void*)mma_gemm<1, 1>, cudaFuncAttributeMaxDynamicSharedMemorySize, SMEM_G23);
    cudaFuncSetAttribute((const void*)mma_gemm<2, 1>, cudaFuncAttributeMaxDynamicSharedMemorySize, SMEM_G23);

    // conversions
    conv_q<<<(unsigned)((size_t)TT * BB * DD / 1024), 256>>>(Q);
    conv_c_ct<<<dim3(DD / 32, SS / 32, BB), dim3(32, 8)>>>(C);
    conv_w<<<(unsigned)((size_t)DD * KK2 / 1024), 256>>>(W);

    // GEMM1: scores = q . c   (2-pass: qh*ch + ql*ch, KC64/NSTG2 — R10 config)
    mma_gemm<0, 2><<<dim3(SS / 128, TT / 128, BB), 256, SMEM_G1>>>(
        (const __half*)pCombH + DD, (const __half*)pCombL + DD,
        (size_t)KK2, (size_t)TT * KK2,
        (const __half*)pCH,
        (size_t)DD, (size_t)SS * DD,
        DD / 64,
        (float*)pScores, nullptr, (size_t)SS, (size_t)TT * SS, nullptr);

    softmax_mask<<<BB * TT, 256>>>();

    // GEMM2: mix = P . cT   (1-pass fp16) -> fp16 into comb cols [0,1024)
    mma_gemm<1, 1><<<dim3(DD / 128, TT / 128, BB), 256, SMEM_G23>>>(
        (const __half*)pPH, nullptr,
        (size_t)SS, (size_t)TT * SS,
        (const __half*)pCTH,
        (size_t)SS, (size_t)DD * SS,
        SS / 64,
        nullptr, (__half*)pCombH, (size_t)KK2, (size_t)TT * KK2, nullptr);

    // GEMM3: out = tanh(comb . W^T + bias)   (1-pass fp16)
    mma_gemm<2, 1><<<dim3(DD / 128, TT / 128, BB), 256, SMEM_G23>>>(
        (const __half*)pCombH, nullptr,
        (size_t)KK2, (size_t)TT * KK2,
        (const __half*)pWH,
        (size_t)KK2, (size_t)0,
        KK2 / 64,
        out, nullptr, (size_t)DD, (size_t)TT * DD, bias);
}

// round 16
// speedup vs baseline: 2.1747x; 1.0006x over previous
#include <cuda_runtime.h>
#include <cuda_fp16.h>
#include <math.h>
#include <stdint.h>

#define TT 2048
#define SS 2048
#define BB 16
#define DD 1024
#define KK2 2048

// ---------------- device scratch (static) ----------------
__device__ float  g_scores[(size_t)BB * TT * SS];   // 256 MiB
__device__ __half g_combH[(size_t)BB * TT * KK2];   // [b][t][0..1023]=mix, [1024..2047]=q
__device__ __half g_combL[(size_t)BB * TT * KK2];   // lo: only q-half used (GEMM1 A)
__device__ __half g_cH[(size_t)BB * SS * DD];       // context hi [b][s][d]
__device__ __half g_cTH[(size_t)BB * DD * SS];      // context^T hi [b][d][s]
__device__ __half g_PH[(size_t)BB * TT * SS];       // probs hi
__device__ __half g_WH[(size_t)DD * KK2];

// ---------------- helpers ----------------
__device__ __forceinline__ void split2(float x, __half& h, __half& l) {
    h = __float2half_rn(x);
    l = __float2half_rn(x - __half2float(h));
}

__device__ __forceinline__ uint32_t smem_u32(const void* p) {
    uint32_t a;
    asm("{ .reg .u64 t; cvta.to.shared.u64 t, %1; cvt.u32.u64 %0, t; }" : "=r"(a) : "l"(p));
    return a;
}

__device__ __forceinline__ void ldsm4(uint32_t* r, uint32_t addr) {
    asm volatile("ldmatrix.sync.aligned.m8n8.x4.shared.b16 {%0,%1,%2,%3}, [%4];"
                 : "=r"(r[0]), "=r"(r[1]), "=r"(r[2]), "=r"(r[3]) : "r"(addr));
}

__device__ __forceinline__ void mma_f16(float* c, const uint32_t* a, uint32_t b0, uint32_t b1) {
    asm volatile(
        "mma.sync.aligned.m16n8k16.row.col.f32.f16.f16.f32 "
        "{%0,%1,%2,%3}, {%4,%5,%6,%7}, {%8,%9}, {%0,%1,%2,%3};"
        : "+f"(c[0]), "+f"(c[1]), "+f"(c[2]), "+f"(c[3])
        : "r"(a[0]), "r"(a[1]), "r"(a[2]), "r"(a[3]), "r"(b0), "r"(b1));
}

// KC=64: 128B rows, 8-sub XOR swizzle (validated R4..R13)
__device__ __forceinline__ uint32_t sw_off64(int r, int c16) {
    return ((uint32_t)r << 7) + (((uint32_t)(c16 ^ (r & 7))) << 4);
}

// ---------------- fused split-precision fp16 mma.sync GEMM ----------------
// NP=2: Ah*Bh + Al*Bh     NP=1: Ah*Bh     (KC=64 only — the validated-best shape)
// CTA tile M128 x N128, 8 warps (4x2, warp 32x64), 2 CTAs/SM.
// EPI: 0 = fp32 streaming store (scores), 1 = fp16 store, 2 = bias+tanh fp32.
template <int EPI, int NP>
__global__ __launch_bounds__(256, 2) void mma_gemm(
    const __half* __restrict__ Ah, const __half* __restrict__ Al,
    size_t a_row, size_t a_batch,
    const __half* __restrict__ Bh,
    size_t b_row, size_t b_batch,
    int KCH,  // K / 64
    float* __restrict__ outF, __half* __restrict__ outH,
    size_t c_row, size_t c_batch, const float* __restrict__ bias) {
    constexpr int NT = (NP == 2) ? 3 : 2;     // tiles per stage
    constexpr int NSTG = (NP == 2) ? 2 : 3;   // R10-validated ring depths
    constexpr uint32_t TILE_B = 16384;        // 128 rows x 128B
    constexpr uint32_t STAGE_B = NT * TILE_B;
    constexpr uint32_t AL_OFF = TILE_B;
    constexpr uint32_t BH_OFF = (NP == 2) ? 2 * TILE_B : TILE_B;

    extern __shared__ char smem[];
    const uint32_t sb = smem_u32(smem);
    const int tid = threadIdx.x;
    const int lane = tid & 31, wid = tid >> 5;
    const int wm = wid & 3, wn = wid >> 2;
    const int n0 = blockIdx.x * 128, m0 = blockIdx.y * 128, bz = blockIdx.z;

    const __half* A_h = Ah + (size_t)bz * a_batch + (size_t)m0 * a_row;
    const __half* A_l = (NP == 2) ? (Al + (size_t)bz * a_batch + (size_t)m0 * a_row) : nullptr;
    const __half* B_h = Bh + (size_t)bz * b_batch + (size_t)n0 * b_row;

    auto load_tile = [&](uint32_t dst, const __half* g, size_t rstride, int kk) {
#pragma unroll
        for (int i = tid; i < 1024; i += 256) {
            const int r = i >> 3, cc = i & 7;
            const char* gp = (const char*)(g + (size_t)r * rstride + kk) + (cc << 4);
            asm volatile("cp.async.cg.shared.global [%0], [%1], 16;"
                         :: "r"(dst + sw_off64(r, cc)), "l"(gp) : "memory");
        }
    };
    auto load_stage = [&](int c) {
        const int kk = c * 64;
        const uint32_t st = sb + (uint32_t)(c % NSTG) * STAGE_B;
        load_tile(st, A_h, a_row, kk);
        if (NP == 2) load_tile(st + AL_OFF, A_l, a_row, kk);
        load_tile(st + BH_OFF, B_h, b_row, kk);
        asm volatile("cp.async.commit_group;" ::: "memory");
    };

    // per-thread ldmatrix offsets (k16 step j via XOR j<<5)
    uint32_t offA[2], offB[4];
    {
        const int gA = lane >> 4;
#pragma unroll
        for (int mi = 0; mi < 2; mi++)
            offA[mi] = sw_off64(wm * 32 + mi * 16 + (lane & 15), gA);
        const int gB = (lane >> 3) & 1;
        const int rb = wn * 64 + ((lane >> 4) << 3) + (lane & 7);
#pragma unroll
        for (int nj = 0; nj < 4; nj++) offB[nj] = sw_off64(rb + nj * 16, gB);
    }

    float acc[2][8][4];
#pragma unroll
    for (int i = 0; i < 2; i++)
#pragma unroll
        for (int j = 0; j < 8; j++)
#pragma unroll
            for (int q = 0; q < 4; q++) acc[i][j][q] = 0.0f;

#pragma unroll
    for (int s = 0; s < NSTG - 1; s++) load_stage(s);

    for (int c = 0; c < KCH; c++) {
        asm volatile("cp.async.wait_group %0;" :: "n"(NSTG - 2) : "memory");
        __syncthreads();
        if (c + NSTG - 1 < KCH) load_stage(c + NSTG - 1);
        else asm volatile("cp.async.commit_group;" ::: "memory");

        const uint32_t st = sb + (uint32_t)(c % NSTG) * STAGE_B;
#pragma unroll
        for (int k16 = 0; k16 < 4; k16++) {
            const uint32_t x = (uint32_t)(k16 << 5);
            uint32_t ah[2][4], al[2][4];
            ldsm4(ah[0], st + (offA[0] ^ x));
            ldsm4(ah[1], st + (offA[1] ^ x));
            if (NP == 2) {
                ldsm4(al[0], st + AL_OFF + (offA[0] ^ x));
                ldsm4(al[1], st + AL_OFF + (offA[1] ^ x));
            }
#pragma unroll
            for (int nj = 0; nj < 4; nj++) {
                uint32_t bh[4];
                ldsm4(bh, st + BH_OFF + (offB[nj] ^ x));
                mma_f16(acc[0][2 * nj], ah[0], bh[0], bh[1]);
                mma_f16(acc[0][2 * nj + 1], ah[0], bh[2], bh[3]);
                mma_f16(acc[1][2 * nj], ah[1], bh[0], bh[1]);
                mma_f16(acc[1][2 * nj + 1], ah[1], bh[2], bh[3]);
                if (NP == 2) {
                    mma_f16(acc[0][2 * nj], al[0], bh[0], bh[1]);
                    mma_f16(acc[0][2 * nj + 1], al[0], bh[2], bh[3]);
                    mma_f16(acc[1][2 * nj], al[1], bh[0], bh[1]);
                    mma_f16(acc[1][2 * nj + 1], al[1], bh[2], bh[3]);
                }
            }
        }
    }

    // -------- epilogue --------
    const int trow = lane >> 2, tcol = (lane & 3) * 2;
#pragma unroll
    for (int mi = 0; mi < 2; mi++) {
#pragma unroll
        for (int nj = 0; nj < 8; nj++) {
            const int row = m0 + wm * 32 + mi * 16 + trow;
            const int col = n0 + wn * 64 + nj * 8 + tcol;
            const float* a4 = acc[mi][nj];
            if (EPI == 0) {
                float* p = outF + (size_t)bz * c_batch + (size_t)row * c_row + col;
                __stcs((float2*)p, make_float2(a4[0], a4[1]));
                __stcs((float2*)(p + 8 * c_row), make_float2(a4[2], a4[3]));
            } else if (EPI == 1) {
                __half* ph = outH + (size_t)bz * c_batch + (size_t)row * c_row + col;
                __half2 vh;
                vh.x = __float2half_rn(a4[0]);
                vh.y = __float2half_rn(a4[1]);
                *(__half2*)ph = vh;
                vh.x = __float2half_rn(a4[2]);
                vh.y = __float2half_rn(a4[3]);
                *(__half2*)(ph + 8 * c_row) = vh;
            } else {
                const float b0 = bias[col], b1 = bias[col + 1];
                float* p = outF + (size_t)bz * c_batch + (size_t)row * c_row + col;
                *(float2*)p = make_float2(tanhf(a4[0] + b0), tanhf(a4[1] + b1));
                *(float2*)(p + 8 * c_row) = make_float2(tanhf(a4[2] + b0), tanhf(a4[3] + b1));
            }
        }
    }
}

// ---------------- conversion kernels (vectorized) ----------------
__global__ __launch_bounds__(256) void conv_q(const float* __restrict__ Q) {
    size_t i4 = ((size_t)blockIdx.x * 256 + threadIdx.x) * 4;  // over T*B*D
    float4 v = *(const float4*)(Q + i4);
    int d = (int)(i4 & (DD - 1));
    size_t j = i4 >> 10;
    int b = (int)(j & (BB - 1));
    size_t t = j >> 4;
    size_t o = ((size_t)b * TT + t) * KK2 + DD + d;
    __half h0, l0, h1, l1;
    __half2 vh, vl;
    split2(v.x, h0, l0); split2(v.y, h1, l1);
    vh.x = h0; vh.y = h1; vl.x = l0; vl.y = l1;
    *(__half2*)(g_combH + o) = vh;
    *(__half2*)(g_combL + o) = vl;
    split2(v.z, h0, l0); split2(v.w, h1, l1);
    vh.x = h0; vh.y = h1; vl.x = l0; vl.y = l1;
    *(__half2*)(g_combH + o + 2) = vh;
    *(__half2*)(g_combL + o + 2) = vl;
}

__global__ __launch_bounds__(256) void conv_c_ct(const float* __restrict__ C) {
    __shared__ float tile[32][33];
    const int b = blockIdx.z;
    const int d0 = blockIdx.x * 32, s0 = blockIdx.y * 32;
    const int tx = threadIdx.x, ty = threadIdx.y;  // (32,8)
#pragma unroll
    for (int i = 0; i < 4; i++) {
        int s = s0 + ty + i * 8;
        float v = C[((size_t)s * BB + b) * DD + d0 + tx];
        tile[ty + i * 8][tx] = v;
        size_t o = ((size_t)b * SS + s) * DD + d0 + tx;
        g_cH[o] = __float2half_rn(v);
    }
    __syncthreads();
#pragma unroll
    for (int i = 0; i < 4; i++) {
        int d = d0 + ty + i * 8;
        size_t o = ((size_t)b * DD + d) * SS + s0 + tx;
        g_cTH[o] = __float2half_rn(tile[tx][ty + i * 8]);
    }
}

__global__ __launch_bounds__(256) void conv_w(const float* __restrict__ W) {
    size_t i4 = ((size_t)blockIdx.x * 256 + threadIdx.x) * 4;  // over D*2D
    float4 v = *(const float4*)(W + i4);
    __half2 vh;
    vh.x = __float2half_rn(v.x);
    vh.y = __float2half_rn(v.y);
    *(__half2*)(g_WH + i4) = vh;
    vh.x = __float2half_rn(v.z);
    vh.y = __float2half_rn(v.w);
    *(__half2*)(g_WH + i4 + 2) = vh;
}

// ---------------- softmax (==0 -> -inf mask), fp32 scores -> fp16 probs ----------------
__global__ __launch_bounds__(256) void softmax_mask() {
    const size_t rowi = blockIdx.x;
    const float4* p4 = (const float4*)(g_scores + rowi * SS);
    __half2* ph2 = (__half2*)(g_PH + rowi * SS);
    const int tid = threadIdx.x;
    const int lane = tid & 31, wid = tid >> 5;
    __shared__ float red[256];
    float4 v[2];
    float m = -INFINITY;
#pragma unroll
    for (int i = 0; i < 2; i++) {
        v[i] = __ldcs(&p4[tid + i * 256]);
        float* f = (float*)&v[i];
#pragma unroll
        for (int q = 0; q < 4; q++) {
            float x = (f[q] == 0.0f) ? -INFINITY : f[q];
            m = fmaxf(m, x);
        }
    }
    // max: warp shuffle (order-exact) + cross-warp via smem (validated R12/R13)
#pragma unroll
    for (int off = 16; off > 0; off >>= 1)
        m = fmaxf(m, __shfl_xor_sync(0xffffffffu, m, off));
    if (lane == 0) red[wid] = m;
    __syncthreads();
    m = red[0];
#pragma unroll
    for (int w = 1; w < 8; w++) m = fmaxf(m, red[w]);
    __syncthreads();
    // exp + sum (tree kept bit-identical to prior rounds)
    float e[8];
    float sum = 0.0f;
#pragma unroll
    for (int i = 0; i < 2; i++) {
        float* f = (float*)&v[i];
#pragma unroll
        for (int q = 0; q < 4; q++) {
            float x = (f[q] == 0.0f) ? 0.0f : __expf(f[q] - m);
            e[i * 4 + q] = x;
            sum += x;
        }
    }
    red[tid] = sum;
    __syncthreads();
#pragma unroll
    for (int s = 128; s > 0; s >>= 1) {
        if (tid < s) red[tid] += red[tid + s];
        __syncthreads();
    }
    const float inv = 1.0f / red[0];
#pragma unroll
    for (int i = 0; i < 2; i++) {
#pragma unroll
        for (int q = 0; q < 2; q++) {
            __half2 vh;
            vh.x = __float2half_rn(e[i * 4 + q * 2] * inv);
            vh.y = __float2half_rn(e[i * 4 + q * 2 + 1] * inv);
            ph2[(tid + i * 256) * 2 + q] = vh;
        }
    }
}

// ---------------- launch ----------------
#define SMEM_G1 98304   // NP2 KC64: 2 stages x 48KB  (R10-validated best)
#define SMEM_G23 98304  // NP1 KC64: 3 stages x 32KB

extern "C" void kernel_launch(void* const* d_in, const int* in_sizes, int n_in,
                              void* d_out, int out_size) {
    (void)in_sizes; (void)n_in; (void)out_size;
    const float* Q = (const float*)d_in[0];
    const float* C = (const float*)d_in[1];
    const float* W = (const float*)d_in[2];
    const float* bias = (const float*)d_in[3];
    float* out = (float*)d_out;

    void *pScores, *pCombH, *pCombL, *pCH, *pCTH, *pPH, *pWH;
    cudaGetSymbolAddress(&pScores, g_scores);
    cudaGetSymbolAddress(&pCombH, g_combH);
    cudaGetSymbolAddress(&pCombL, g_combL);
    cudaGetSymbolAddress(&pCH, g_cH);
    cudaGetSymbolAddress(&pCTH, g_cTH);
    cudaGetSymbolAddress(&pPH, g_PH);
    cudaGetSymbolAddress(&pWH, g_WH);

    cudaFuncSetAttribute((const void*)mma_gemm<0, 2>, cudaFuncAttributeMaxDynamicSharedMemorySize, SMEM_G1);
    cudaFuncSetAttribute((const void*)mma_gemm<1, 1>, cudaFuncAttributeMaxDynamicSharedMemorySize, SMEM_G23);
    cudaFuncSetAttribute((const void*)mma_gemm<2, 1>, cudaFuncAttributeMaxDynamicSharedMemorySize, SMEM_G23);

    // conversions
    conv_q<<<(unsigned)((size_t)TT * BB * DD / 1024), 256>>>(Q);
    conv_c_ct<<<dim3(DD / 32, SS / 32, BB), dim3(32, 8)>>>(C);
    conv_w<<<(unsigned)((size_t)DD * KK2 / 1024), 256>>>(W);

    // GEMM1: scores = q . c   (2-pass: qh*ch + ql*ch, KC64/NSTG2 — R10 config)
    mma_gemm<0, 2><<<dim3(SS / 128, TT / 128, BB), 256, SMEM_G1>>>(
        (const __half*)pCombH + DD, (const __half*)pCombL + DD,
        (size_t)KK2, (size_t)TT * KK2,
        (const __half*)pCH,
        (size_t)DD, (size_t)SS * DD,
        DD / 64,
        (float*)pScores, nullptr, (size_t)SS, (size_t)TT * SS, nullptr);

    softmax_mask<<<BB * TT, 256>>>();

    // GEMM2: mix = P . cT   (1-pass fp16) -> fp16 into comb cols [0,1024)
    mma_gemm<1, 1><<<dim3(DD / 128, TT / 128, BB), 256, SMEM_G23>>>(
        (const __half*)pPH, nullptr,
        (size_t)SS, (size_t)TT * SS,
        (const __half*)pCTH,
        (size_t)SS, (size_t)DD * SS,
        SS / 64,
        nullptr, (__half*)pCombH, (size_t)KK2, (size_t)TT * KK2, nullptr);

    // GEMM3: out = tanh(comb . W^T + bias)   (1-pass fp16)
    mma_gemm<2, 1><<<dim3(DD / 128, TT / 128, BB), 256, SMEM_G23>>>(
        (const __half*)pCombH, nullptr,
        (size_t)KK2, (size_t)TT * KK2,
        (const __half*)pWH,
        (size_t)KK2, (size_t)0,
        KK2 / 64,
        out, nullptr, (size_t)DD, (size_t)TT * DD, bias);
}

// round 17
// speedup vs baseline: 2.1766x; 1.0009x over previous
#include <cuda_runtime.h>
#include <cuda_fp16.h>
#include <math.h>
#include <stdint.h>

#define TT 2048
#define SS 2048
#define BB 16
#define DD 1024
#define KK2 2048

// ---------------- device scratch (static) ----------------
__device__ float  g_scores[(size_t)BB * TT * SS];   // 256 MiB
__device__ __half g_combH[(size_t)BB * TT * KK2];   // [b][t][0..1023]=mix, [1024..2047]=q
__device__ __half g_combL[(size_t)BB * TT * KK2];   // lo: only q-half used (GEMM1 A)
__device__ __half g_cH[(size_t)BB * SS * DD];       // context hi [b][s][d]
__device__ __half g_cTH[(size_t)BB * DD * SS];      // context^T hi [b][d][s]
__device__ __half g_PH[(size_t)BB * TT * SS];       // probs hi
__device__ __half g_WH[(size_t)DD * KK2];

// ---------------- helpers ----------------
__device__ __forceinline__ void split2(float x, __half& h, __half& l) {
    h = __float2half_rn(x);
    l = __float2half_rn(x - __half2float(h));
}

__device__ __forceinline__ uint32_t smem_u32(const void* p) {
    uint32_t a;
    asm("{ .reg .u64 t; cvta.to.shared.u64 t, %1; cvt.u32.u64 %0, t; }" : "=r"(a) : "l"(p));
    return a;
}

__device__ __forceinline__ void ldsm4(uint32_t* r, uint32_t addr) {
    asm volatile("ldmatrix.sync.aligned.m8n8.x4.shared.b16 {%0,%1,%2,%3}, [%4];"
                 : "=r"(r[0]), "=r"(r[1]), "=r"(r[2]), "=r"(r[3]) : "r"(addr));
}

__device__ __forceinline__ void mma_f16(float* c, const uint32_t* a, uint32_t b0, uint32_t b1) {
    asm volatile(
        "mma.sync.aligned.m16n8k16.row.col.f32.f16.f16.f32 "
        "{%0,%1,%2,%3}, {%4,%5,%6,%7}, {%8,%9}, {%0,%1,%2,%3};"
        : "+f"(c[0]), "+f"(c[1]), "+f"(c[2]), "+f"(c[3])
        : "r"(a[0]), "r"(a[1]), "r"(a[2]), "r"(a[3]), "r"(b0), "r"(b1));
}

// KC=64: 128B rows, 8-sub XOR swizzle (validated R4..R13)
__device__ __forceinline__ uint32_t sw_off64(int r, int c16) {
    return ((uint32_t)r << 7) + (((uint32_t)(c16 ^ (r & 7))) << 4);
}

// ---------------- fused split-precision fp16 mma.sync GEMM ----------------
// NP=2: Ah*Bh + Al*Bh     NP=1: Ah*Bh     (KC=64 only — the validated-best shape)
// CTA tile M128 x N128, 8 warps (4x2, warp 32x64), 2 CTAs/SM.
// EPI: 0 = fp32 streaming store (scores), 1 = fp16 store, 2 = bias+tanh fp32.
template <int EPI, int NP>
__global__ __launch_bounds__(256, 2) void mma_gemm(
    const __half* __restrict__ Ah, const __half* __restrict__ Al,
    size_t a_row, size_t a_batch,
    const __half* __restrict__ Bh,
    size_t b_row, size_t b_batch,
    int KCH,  // K / 64
    float* __restrict__ outF, __half* __restrict__ outH,
    size_t c_row, size_t c_batch, const float* __restrict__ bias) {
    constexpr int NT = (NP == 2) ? 3 : 2;     // tiles per stage
    constexpr int NSTG = (NP == 2) ? 2 : 3;   // R10-validated ring depths
    constexpr uint32_t TILE_B = 16384;        // 128 rows x 128B
    constexpr uint32_t STAGE_B = NT * TILE_B;
    constexpr uint32_t AL_OFF = TILE_B;
    constexpr uint32_t BH_OFF = (NP == 2) ? 2 * TILE_B : TILE_B;

    extern __shared__ char smem[];
    const uint32_t sb = smem_u32(smem);
    const int tid = threadIdx.x;
    const int lane = tid & 31, wid = tid >> 5;
    const int wm = wid & 3, wn = wid >> 2;
    const int n0 = blockIdx.x * 128, m0 = blockIdx.y * 128, bz = blockIdx.z;

    const __half* A_h = Ah + (size_t)bz * a_batch + (size_t)m0 * a_row;
    const __half* A_l = (NP == 2) ? (Al + (size_t)bz * a_batch + (size_t)m0 * a_row) : nullptr;
    const __half* B_h = Bh + (size_t)bz * b_batch + (size_t)n0 * b_row;

    auto load_tile = [&](uint32_t dst, const __half* g, size_t rstride, int kk) {
#pragma unroll
        for (int i = tid; i < 1024; i += 256) {
            const int r = i >> 3, cc = i & 7;
            const char* gp = (const char*)(g + (size_t)r * rstride + kk) + (cc << 4);
            asm volatile("cp.async.cg.shared.global [%0], [%1], 16;"
                         :: "r"(dst + sw_off64(r, cc)), "l"(gp) : "memory");
        }
    };
    auto load_stage = [&](int c) {
        const int kk = c * 64;
        const uint32_t st = sb + (uint32_t)(c % NSTG) * STAGE_B;
        load_tile(st, A_h, a_row, kk);
        if (NP == 2) load_tile(st + AL_OFF, A_l, a_row, kk);
        load_tile(st + BH_OFF, B_h, b_row, kk);
        asm volatile("cp.async.commit_group;" ::: "memory");
    };

    // per-thread ldmatrix offsets (k16 step j via XOR j<<5)
    uint32_t offA[2], offB[4];
    {
        const int gA = lane >> 4;
#pragma unroll
        for (int mi = 0; mi < 2; mi++)
            offA[mi] = sw_off64(wm * 32 + mi * 16 + (lane & 15), gA);
        const int gB = (lane >> 3) & 1;
        const int rb = wn * 64 + ((lane >> 4) << 3) + (lane & 7);
#pragma unroll
        for (int nj = 0; nj < 4; nj++) offB[nj] = sw_off64(rb + nj * 16, gB);
    }

    float acc[2][8][4];
#pragma unroll
    for (int i = 0; i < 2; i++)
#pragma unroll
        for (int j = 0; j < 8; j++)
#pragma unroll
            for (int q = 0; q < 4; q++) acc[i][j][q] = 0.0f;

#pragma unroll
    for (int s = 0; s < NSTG - 1; s++) load_stage(s);

    for (int c = 0; c < KCH; c++) {
        asm volatile("cp.async.wait_group %0;" :: "n"(NSTG - 2) : "memory");
        __syncthreads();
        if (c + NSTG - 1 < KCH) load_stage(c + NSTG - 1);
        else asm volatile("cp.async.commit_group;" ::: "memory");

        const uint32_t st = sb + (uint32_t)(c % NSTG) * STAGE_B;
#pragma unroll
        for (int k16 = 0; k16 < 4; k16++) {
            const uint32_t x = (uint32_t)(k16 << 5);
            uint32_t ah[2][4], al[2][4];
            ldsm4(ah[0], st + (offA[0] ^ x));
            ldsm4(ah[1], st + (offA[1] ^ x));
            if (NP == 2) {
                ldsm4(al[0], st + AL_OFF + (offA[0] ^ x));
                ldsm4(al[1], st + AL_OFF + (offA[1] ^ x));
            }
#pragma unroll
            for (int nj = 0; nj < 4; nj++) {
                uint32_t bh[4];
                ldsm4(bh, st + BH_OFF + (offB[nj] ^ x));
                mma_f16(acc[0][2 * nj], ah[0], bh[0], bh[1]);
                mma_f16(acc[0][2 * nj + 1], ah[0], bh[2], bh[3]);
                mma_f16(acc[1][2 * nj], ah[1], bh[0], bh[1]);
                mma_f16(acc[1][2 * nj + 1], ah[1], bh[2], bh[3]);
                if (NP == 2) {
                    mma_f16(acc[0][2 * nj], al[0], bh[0], bh[1]);
                    mma_f16(acc[0][2 * nj + 1], al[0], bh[2], bh[3]);
                    mma_f16(acc[1][2 * nj], al[1], bh[0], bh[1]);
                    mma_f16(acc[1][2 * nj + 1], al[1], bh[2], bh[3]);
                }
            }
        }
    }

    // -------- epilogue --------
    const int trow = lane >> 2, tcol = (lane & 3) * 2;
#pragma unroll
    for (int mi = 0; mi < 2; mi++) {
#pragma unroll
        for (int nj = 0; nj < 8; nj++) {
            const int row = m0 + wm * 32 + mi * 16 + trow;
            const int col = n0 + wn * 64 + nj * 8 + tcol;
            const float* a4 = acc[mi][nj];
            if (EPI == 0) {
                float* p = outF + (size_t)bz * c_batch + (size_t)row * c_row + col;
                __stcs((float2*)p, make_float2(a4[0], a4[1]));
                __stcs((float2*)(p + 8 * c_row), make_float2(a4[2], a4[3]));
            } else if (EPI == 1) {
                __half* ph = outH + (size_t)bz * c_batch + (size_t)row * c_row + col;
                __half2 vh;
                vh.x = __float2half_rn(a4[0]);
                vh.y = __float2half_rn(a4[1]);
                *(__half2*)ph = vh;
                vh.x = __float2half_rn(a4[2]);
                vh.y = __float2half_rn(a4[3]);
                *(__half2*)(ph + 8 * c_row) = vh;
            } else {
                const float b0 = bias[col], b1 = bias[col + 1];
                float* p = outF + (size_t)bz * c_batch + (size_t)row * c_row + col;
                *(float2*)p = make_float2(tanhf(a4[0] + b0), tanhf(a4[1] + b1));
                *(float2*)(p + 8 * c_row) = make_float2(tanhf(a4[2] + b0), tanhf(a4[3] + b1));
            }
        }
    }
}

// ---------------- conversion kernels (vectorized) ----------------
__global__ __launch_bounds__(256) void conv_q(const float* __restrict__ Q) {
    size_t i4 = ((size_t)blockIdx.x * 256 + threadIdx.x) * 4;  // over T*B*D
    float4 v = *(const float4*)(Q + i4);
    int d = (int)(i4 & (DD - 1));
    size_t j = i4 >> 10;
    int b = (int)(j & (BB - 1));
    size_t t = j >> 4;
    size_t o = ((size_t)b * TT + t) * KK2 + DD + d;
    __half h0, l0, h1, l1;
    __half2 vh, vl;
    split2(v.x, h0, l0); split2(v.y, h1, l1);
    vh.x = h0; vh.y = h1; vl.x = l0; vl.y = l1;
    *(__half2*)(g_combH + o) = vh;
    *(__half2*)(g_combL + o) = vl;
    split2(v.z, h0, l0); split2(v.w, h1, l1);
    vh.x = h0; vh.y = h1; vl.x = l0; vl.y = l1;
    *(__half2*)(g_combH + o + 2) = vh;
    *(__half2*)(g_combL + o + 2) = vl;
}

__global__ __launch_bounds__(256) void conv_c_ct(const float* __restrict__ C) {
    __shared__ float tile[32][33];
    const int b = blockIdx.z;
    const int d0 = blockIdx.x * 32, s0 = blockIdx.y * 32;
    const int tx = threadIdx.x, ty = threadIdx.y;  // (32,8)
#pragma unroll
    for (int i = 0; i < 4; i++) {
        int s = s0 + ty + i * 8;
        float v = C[((size_t)s * BB + b) * DD + d0 + tx];
        tile[ty + i * 8][tx] = v;
        size_t o = ((size_t)b * SS + s) * DD + d0 + tx;
        g_cH[o] = __float2half_rn(v);
    }
    __syncthreads();
#pragma unroll
    for (int i = 0; i < 4; i++) {
        int d = d0 + ty + i * 8;
        size_t o = ((size_t)b * DD + d) * SS + s0 + tx;
        g_cTH[o] = __float2half_rn(tile[tx][ty + i * 8]);
    }
}

__global__ __launch_bounds__(256) void conv_w(const float* __restrict__ W) {
    size_t i4 = ((size_t)blockIdx.x * 256 + threadIdx.x) * 4;  // over D*2D
    float4 v = *(const float4*)(W + i4);
    __half2 vh;
    vh.x = __float2half_rn(v.x);
    vh.y = __float2half_rn(v.y);
    *(__half2*)(g_WH + i4) = vh;
    vh.x = __float2half_rn(v.z);
    vh.y = __float2half_rn(v.w);
    *(__half2*)(g_WH + i4 + 2) = vh;
}

// ---------------- softmax (==0 -> -inf mask), fp32 scores -> fp16 probs ----------------
__global__ __launch_bounds__(256) void softmax_mask() {
    const size_t rowi = blockIdx.x;
    const float4* p4 = (const float4*)(g_scores + rowi * SS);
    __half2* ph2 = (__half2*)(g_PH + rowi * SS);
    const int tid = threadIdx.x;
    const int lane = tid & 31, wid = tid >> 5;
    __shared__ float red[256];
    float4 v[2];
    float m = -INFINITY;
#pragma unroll
    for (int i = 0; i < 2; i++) {
        v[i] = __ldcs(&p4[tid + i * 256]);
        float* f = (float*)&v[i];
#pragma unroll
        for (int q = 0; q < 4; q++) {
            float x = (f[q] == 0.0f) ? -INFINITY : f[q];
            m = fmaxf(m, x);
        }
    }
    // max: warp shuffle (order-exact) + cross-warp via smem (validated R12/R13)
#pragma unroll
    for (int off = 16; off > 0; off >>= 1)
        m = fmaxf(m, __shfl_xor_sync(0xffffffffu, m, off));
    if (lane == 0) red[wid] = m;
    __syncthreads();
    m = red[0];
#pragma unroll
    for (int w = 1; w < 8; w++) m = fmaxf(m, red[w]);
    __syncthreads();
    // exp + sum (tree kept bit-identical to prior rounds)
    float e[8];
    float sum = 0.0f;
#pragma unroll
    for (int i = 0; i < 2; i++) {
        float* f = (float*)&v[i];
#pragma unroll
        for (int q = 0; q < 4; q++) {
            float x = (f[q] == 0.0f) ? 0.0f : __expf(f[q] - m);
            e[i * 4 + q] = x;
            sum += x;
        }
    }
    red[tid] = sum;
    __syncthreads();
#pragma unroll
    for (int s = 128; s > 0; s >>= 1) {
        if (tid < s) red[tid] += red[tid + s];
        __syncthreads();
    }
    const float inv = 1.0f / red[0];
#pragma unroll
    for (int i = 0; i < 2; i++) {
#pragma unroll
        for (int q = 0; q < 2; q++) {
            __half2 vh;
            vh.x = __float2half_rn(e[i * 4 + q * 2] * inv);
            vh.y = __float2half_rn(e[i * 4 + q * 2 + 1] * inv);
            ph2[(tid + i * 256) * 2 + q] = vh;
        }
    }
}

// ---------------- launch ----------------
#define SMEM_G1 98304   // NP2 KC64: 2 stages x 48KB  (R10-validated best)
#define SMEM_G23 98304  // NP1 KC64: 3 stages x 32KB

extern "C" void kernel_launch(void* const* d_in, const int* in_sizes, int n_in,
                              void* d_out, int out_size) {
    (void)in_sizes; (void)n_in; (void)out_size;
    const float* Q = (const float*)d_in[0];
    const float* C = (const float*)d_in[1];
    const float* W = (const float*)d_in[2];
    const float* bias = (const float*)d_in[3];
    float* out = (float*)d_out;

    void *pScores, *pCombH, *pCombL, *pCH, *pCTH, *pPH, *pWH;
    cudaGetSymbolAddress(&pScores, g_scores);
    cudaGetSymbolAddress(&pCombH, g_combH);
    cudaGetSymbolAddress(&pCombL, g_combL);
    cudaGetSymbolAddress(&pCH, g_cH);
    cudaGetSymbolAddress(&pCTH, g_cTH);
    cudaGetSymbolAddress(&pPH, g_PH);
    cudaGetSymbolAddress(&pWH, g_WH);

    cudaFuncSetAttribute((const void*)mma_gemm<0, 2>, cudaFuncAttributeMaxDynamicSharedMemorySize, SMEM_G1);
    cudaFuncSetAttribute((const void*)mma_gemm<1, 1>, cudaFuncAttributeMaxDynamicSharedMemorySize, SMEM_G23);
    cudaFuncSetAttribute((const void*)mma_gemm<2, 1>, cudaFuncAttributeMaxDynamicSharedMemorySize, SMEM_G23);

    // conversions
    conv_q<<<(unsigned)((size_t)TT * BB * DD / 1024), 256>>>(Q);
    conv_c_ct<<<dim3(DD / 32, SS / 32, BB), dim3(32, 8)>>>(C);
    conv_w<<<(unsigned)((size_t)DD * KK2 / 1024), 256>>>(W);

    // GEMM1: scores = q . c   (2-pass: qh*ch + ql*ch, KC64/NSTG2 — R10 config)
    mma_gemm<0, 2><<<dim3(SS / 128, TT / 128, BB), 256, SMEM_G1>>>(
        (const __half*)pCombH + DD, (const __half*)pCombL + DD,
        (size_t)KK2, (size_t)TT * KK2,
        (const __half*)pCH,
        (size_t)DD, (size_t)SS * DD,
        DD / 64,
        (float*)pScores, nullptr, (size_t)SS, (size_t)TT * SS, nullptr);

    softmax_mask<<<BB * TT, 256>>>();

    // GEMM2: mix = P . cT   (1-pass fp16) -> fp16 into comb cols [0,1024)
    mma_gemm<1, 1><<<dim3(DD / 128, TT / 128, BB), 256, SMEM_G23>>>(
        (const __half*)pPH, nullptr,
        (size_t)SS, (size_t)TT * SS,
        (const __half*)pCTH,
        (size_t)SS, (size_t)DD * SS,
        SS / 64,
        nullptr, (__half*)pCombH, (size_t)KK2, (size_t)TT * KK2, nullptr);

    // GEMM3: out = tanh(comb . W^T + bias)   (1-pass fp16)
    mma_gemm<2, 1><<<dim3(DD / 128, TT / 128, BB), 256, SMEM_G23>>>(
        (const __half*)pCombH, nullptr,
        (size_t)KK2, (size_t)TT * KK2,
        (const __half*)pWH,
        (size_t)KK2, (size_t)0,
        KK2 / 64,
        out, nullptr, (size_t)DD, (size_t)TT * DD, bias);
}